// round 1
// baseline (speedup 1.0000x reference)
#include <cuda_runtime.h>

#define NN 100000
#define EE 800000
#define DD 128
#define TH0 0.5f
#define TH1 0.3f
#define TH2 0.2f
#define NEG 0.01f

#define SA 132                       // padded smem row stride (floats), 16B-aligned rows
#define GEMM_SMEM ((2*128*SA + 128)*4)

// ---------------- scratch (device globals: no allocation allowed) ----------------
__device__ int   g_deg[NN];
__device__ int   g_rowptr[NN + 1];
__device__ int   g_cursor[NN];
__device__ int   g_partials[128];
__device__ int   g_blockoff[128];
__device__ float g_dinv[NN];
__device__ int   g_col[EE];
__device__ float g_xk0[NN * DD];
__device__ float g_xk1[NN * DD];
__device__ float g_hi [NN * DD];
__device__ float g_W1t[DD * DD];      // W1 transposed: [k][n]
__device__ float g_B  [3 * DD * DD];  // combined output matrix (384 x 128)

// ---------------- small prep: W1 transpose + combined B ----------------
// B[j][i]        = lin_w[i][j]                         (j in [0,128))   -> e term
// B[128+j][i]    = sum_k weights[j][k]   * lin_w[i][128+k]              -> hi term
// B[256+j][i]    = sum_k weights[128+j][k]*lin_w[i][128+k]              -> x  term
__global__ void k_prep(const float* __restrict__ w1,
                       const float* __restrict__ lin_w,
                       const float* __restrict__ weights) {
    int bid = blockIdx.x, t = threadIdx.x;
    if (bid < 128) {
        g_W1t[bid * 128 + t] = w1[t * 128 + bid];
    } else {
        int r = bid - 128;             // 0..383
        if (r < 128) {
            g_B[r * 128 + t] = lin_w[t * 256 + r];
        } else {
            int wrow = r - 128;        // 0..255 (rows of `weights`, matching [hi, x])
            float s = 0.f;
            #pragma unroll 4
            for (int k = 0; k < 128; k++)
                s = fmaf(__ldg(&weights[wrow * 128 + k]), __ldg(&lin_w[t * 256 + 128 + k]), s);
            g_B[r * 128 + t] = s;
        }
    }
}

// ---------------- CSR build ----------------
__global__ void k_zero() {
    int i = blockIdx.x * blockDim.x + threadIdx.x;
    if (i < NN) g_deg[i] = 0;
}
__global__ void k_deg(const int* __restrict__ dst) {
    int i = blockIdx.x * blockDim.x + threadIdx.x;
    if (i < EE) atomicAdd(&g_deg[dst[i]], 1);
}
__global__ void k_scan_block() {
    __shared__ int s[1024];
    int i = blockIdx.x * 1024 + threadIdx.x;
    int v = (i < NN) ? g_deg[i] : 0;
    s[threadIdx.x] = v;
    __syncthreads();
    for (int off = 1; off < 1024; off <<= 1) {
        int t = (threadIdx.x >= off) ? s[threadIdx.x - off] : 0;
        __syncthreads();
        s[threadIdx.x] += t;
        __syncthreads();
    }
    if (i < NN) g_rowptr[i] = s[threadIdx.x] - v;          // exclusive
    if (threadIdx.x == 1023) g_partials[blockIdx.x] = s[1023];
}
__global__ void k_scan_top(int nblk) {
    __shared__ int s[128];
    int t = threadIdx.x;
    int v = (t < nblk) ? g_partials[t] : 0;
    s[t] = v;
    __syncthreads();
    for (int off = 1; off < 128; off <<= 1) {
        int u = (t >= off) ? s[t - off] : 0;
        __syncthreads();
        s[t] += u;
        __syncthreads();
    }
    g_blockoff[t] = s[t] - v;                              // exclusive
}
__global__ void k_scan_add() {
    int i = blockIdx.x * 1024 + threadIdx.x;
    if (i < NN) {
        int r = g_rowptr[i] + g_blockoff[blockIdx.x];
        g_rowptr[i] = r;
        g_cursor[i] = r;
        int d = g_deg[i];
        g_dinv[i] = rsqrtf((float)(d > 0 ? d : 1));
        if (i == NN - 1) g_rowptr[NN] = EE;
    }
}
__global__ void k_fill(const int* __restrict__ src, const int* __restrict__ dst) {
    int i = blockIdx.x * blockDim.x + threadIdx.x;
    if (i < EE) {
        int p = atomicAdd(&g_cursor[dst[i]], 1);
        g_col[p] = src[i];
    }
}

// ---------------- fused predictor GEMM: h=relu(x@W1^T+b1) -> prob -> xk0 ----------------
__global__ __launch_bounds__(256, 1)
void k_pred(const float* __restrict__ x, const float* __restrict__ b1,
            const float* __restrict__ w2, const float* __restrict__ b2,
            const float* __restrict__ alpha, const float* __restrict__ emb) {
    extern __shared__ float smem[];
    float* Xs = smem;                // [128][SA]  x tile (row-major [m][k])
    float* Ws = smem + 128 * SA;     // [128][SA]  W1t tile ([k][n]); reused as Hs
    float* Ps = smem + 2 * 128 * SA; // [128] probs

    const int n0 = blockIdx.x * 128;
    const int rows = min(128, NN - n0);
    const int tid = threadIdx.x;

    for (int idx = tid; idx < 128 * 32; idx += 256) {
        int m = idx >> 5, kq = (idx & 31) * 4;
        float4 v = make_float4(0.f, 0.f, 0.f, 0.f);
        if (m < rows) v = *(const float4*)&x[(n0 + m) * 128 + kq];
        *(float4*)&Xs[m * SA + kq] = v;
    }
    for (int idx = tid; idx < 128 * 32; idx += 256) {
        int kk = idx >> 5, nq = (idx & 31) * 4;
        *(float4*)&Ws[kk * SA + nq] = *(const float4*)&g_W1t[kk * 128 + nq];
    }
    __syncthreads();

    const int tx = tid & 15, ty = tid >> 4;
    const int rA0 = ty * 4, rA1 = rA0 + 64;   // 8 rows: split mapping
    const int cB0 = tx * 4, cB1 = cB0 + 64;   // 8 cols: split mapping (bank-phase friendly)

    float acc[64];
    #pragma unroll
    for (int i = 0; i < 64; i++) acc[i] = 0.f;

    #pragma unroll 1
    for (int k0 = 0; k0 < 128; k0 += 4) {
        float a[8][4];
        float bb[4][8];
        #pragma unroll
        for (int r = 0; r < 4; r++) {
            *(float4*)a[r]     = *(const float4*)&Xs[(rA0 + r) * SA + k0];
            *(float4*)a[r + 4] = *(const float4*)&Xs[(rA1 + r) * SA + k0];
        }
        #pragma unroll
        for (int kj = 0; kj < 4; kj++) {
            *(float4*)&bb[kj][0] = *(const float4*)&Ws[(k0 + kj) * SA + cB0];
            *(float4*)&bb[kj][4] = *(const float4*)&Ws[(k0 + kj) * SA + cB1];
        }
        #pragma unroll
        for (int kj = 0; kj < 4; kj++)
            #pragma unroll
            for (int mi = 0; mi < 8; mi++) {
                float av = a[mi][kj];
                #pragma unroll
                for (int ni = 0; ni < 8; ni++)
                    acc[mi * 8 + ni] = fmaf(av, bb[kj][ni], acc[mi * 8 + ni]);
            }
    }

    __syncthreads();                 // done reading Ws; reuse as Hs
    float* Hs = Ws;
    #pragma unroll
    for (int mi = 0; mi < 8; mi++) {
        int r = (mi < 4) ? (rA0 + mi) : (rA1 + mi - 4);
        #pragma unroll
        for (int h = 0; h < 2; h++) {
            int c = h ? cB1 : cB0;
            #pragma unroll
            for (int j = 0; j < 4; j++)
                Hs[r * SA + c + j] = fmaxf(acc[mi * 8 + h * 4 + j] + __ldg(&b1[c + j]), 0.f);
        }
    }
    __syncthreads();

    if (tid < 128) {
        float l0 = __ldg(&b2[0]), l1 = __ldg(&b2[1]);
        #pragma unroll 4
        for (int j = 0; j < 128; j++) {
            float hv = Hs[tid * SA + j];
            l0 = fmaf(hv, __ldg(&w2[j]), l0);
            l1 = fmaf(hv, __ldg(&w2[128 + j]), l1);
        }
        Ps[tid] = 1.f / (1.f + expf(l0 - l1));   // softmax[:,1] for 2 classes
    }
    __syncthreads();

    const float al = __ldg(&alpha[0]);
    for (int idx = tid; idx < 128 * 32; idx += 256) {
        int m = idx >> 5, cq = (idx & 31) * 4;
        if (m < rows) {
            float p = Ps[m];
            float4 xv = *(const float4*)&Xs[m * SA + cq];
            float4 e0 = *(const float4*)&emb[cq];
            float4 e1 = *(const float4*)&emb[128 + cq];
            float4 o;
            o.x = xv.x + al * ((1.f - p) * e0.x + p * e1.x);
            o.y = xv.y + al * ((1.f - p) * e0.y + p * e1.y);
            o.z = xv.z + al * ((1.f - p) * e0.z + p * e1.z);
            o.w = xv.w + al * ((1.f - p) * e0.w + p * e1.w);
            *(float4*)&g_xk0[(n0 + m) * 128 + cq] = o;
        }
    }
}

// ---------------- Laplacian passes (warp per node, CSR gather, no float atomics) ----------------
__global__ __launch_bounds__(256)
void k_lap1() {
    int gw = (blockIdx.x * blockDim.x + threadIdx.x) >> 5;
    if (gw >= NN) return;
    int lane = threadIdx.x & 31;
    const float4* xin = (const float4*)g_xk0;
    int beg = g_rowptr[gw], end = g_rowptr[gw + 1];
    float4 acc = make_float4(0.f, 0.f, 0.f, 0.f);
    for (int ei = beg; ei < end; ei++) {
        int u = __ldg(&g_col[ei]);
        float du = __ldg(&g_dinv[u]);
        float4 xu = __ldg(&xin[u * 32 + lane]);
        acc.x = fmaf(xu.x, du, acc.x); acc.y = fmaf(xu.y, du, acc.y);
        acc.z = fmaf(xu.z, du, acc.z); acc.w = fmaf(xu.w, du, acc.w);
    }
    float dv = g_dinv[gw];
    float4 xv = xin[gw * 32 + lane];
    float4 r;
    r.x = xv.x - acc.x * dv; r.y = xv.y - acc.y * dv;
    r.z = xv.z - acc.z * dv; r.w = xv.w - acc.w * dv;
    ((float4*)g_xk1)[gw * 32 + lane] = r;
}
// hi = TH0*xk0 + TH1*xk1 + TH2*xk2,  xk2 = xk1 - msg*dinv  (fused)
__global__ __launch_bounds__(256)
void k_lap2() {
    int gw = (blockIdx.x * blockDim.x + threadIdx.x) >> 5;
    if (gw >= NN) return;
    int lane = threadIdx.x & 31;
    const float4* x1 = (const float4*)g_xk1;
    int beg = g_rowptr[gw], end = g_rowptr[gw + 1];
    float4 acc = make_float4(0.f, 0.f, 0.f, 0.f);
    for (int ei = beg; ei < end; ei++) {
        int u = __ldg(&g_col[ei]);
        float du = __ldg(&g_dinv[u]);
        float4 xu = __ldg(&x1[u * 32 + lane]);
        acc.x = fmaf(xu.x, du, acc.x); acc.y = fmaf(xu.y, du, acc.y);
        acc.z = fmaf(xu.z, du, acc.z); acc.w = fmaf(xu.w, du, acc.w);
    }
    float dv = g_dinv[gw];
    float4 v0 = ((const float4*)g_xk0)[gw * 32 + lane];
    float4 v1 = x1[gw * 32 + lane];
    const float c1 = TH1 + TH2;
    float4 r;
    r.x = TH0 * v0.x + c1 * v1.x - TH2 * (acc.x * dv);
    r.y = TH0 * v0.y + c1 * v1.y - TH2 * (acc.y * dv);
    r.z = TH0 * v0.z + c1 * v1.z - TH2 * (acc.z * dv);
    r.w = TH0 * v0.w + c1 * v1.w - TH2 * (acc.w * dv);
    ((float4*)g_hi)[gw * 32 + lane] = r;
}

// ---------------- fused final GEMM: out = leaky([e|hi|x] @ B + lin_b) + x0 ----------------
__global__ __launch_bounds__(256, 1)
void k_final(const float* __restrict__ e, const float* __restrict__ x,
             const float* __restrict__ x0, const float* __restrict__ linb,
             float* __restrict__ out) {
    extern __shared__ float smem[];
    float* As = smem;                // [128][SA]
    float* Bs = smem + 128 * SA;     // [128][SA]

    const int n0 = blockIdx.x * 128;
    const int rows = min(128, NN - n0);
    const int tid = threadIdx.x;
    const int tx = tid & 15, ty = tid >> 4;
    const int rA0 = ty * 4, rA1 = rA0 + 64;
    const int cB0 = tx * 4, cB1 = cB0 + 64;

    float acc[64];
    #pragma unroll
    for (int i = 0; i < 64; i++) acc[i] = 0.f;

    for (int s = 0; s < 3; s++) {
        if (s) __syncthreads();
        const float* srcm = (s == 0) ? e : ((s == 1) ? (const float*)g_hi : x);
        for (int idx = tid; idx < 128 * 32; idx += 256) {
            int m = idx >> 5, kq = (idx & 31) * 4;
            float4 v = make_float4(0.f, 0.f, 0.f, 0.f);
            if (m < rows) v = *(const float4*)&srcm[(n0 + m) * 128 + kq];
            *(float4*)&As[m * SA + kq] = v;
        }
        const float* bseg = &g_B[s * 128 * 128];
        for (int idx = tid; idx < 128 * 32; idx += 256) {
            int kk = idx >> 5, nq = (idx & 31) * 4;
            *(float4*)&Bs[kk * SA + nq] = *(const float4*)&bseg[kk * 128 + nq];
        }
        __syncthreads();

        #pragma unroll 1
        for (int k0 = 0; k0 < 128; k0 += 4) {
            float a[8][4];
            float bb[4][8];
            #pragma unroll
            for (int r = 0; r < 4; r++) {
                *(float4*)a[r]     = *(const float4*)&As[(rA0 + r) * SA + k0];
                *(float4*)a[r + 4] = *(const float4*)&As[(rA1 + r) * SA + k0];
            }
            #pragma unroll
            for (int kj = 0; kj < 4; kj++) {
                *(float4*)&bb[kj][0] = *(const float4*)&Bs[(k0 + kj) * SA + cB0];
                *(float4*)&bb[kj][4] = *(const float4*)&Bs[(k0 + kj) * SA + cB1];
            }
            #pragma unroll
            for (int kj = 0; kj < 4; kj++)
                #pragma unroll
                for (int mi = 0; mi < 8; mi++) {
                    float av = a[mi][kj];
                    #pragma unroll
                    for (int ni = 0; ni < 8; ni++)
                        acc[mi * 8 + ni] = fmaf(av, bb[kj][ni], acc[mi * 8 + ni]);
                }
        }
    }

    #pragma unroll
    for (int mi = 0; mi < 8; mi++) {
        int r = (mi < 4) ? (rA0 + mi) : (rA1 + mi - 4);
        if (r < rows) {
            #pragma unroll
            for (int h = 0; h < 2; h++) {
                int c = h ? cB1 : cB0;
                float4 xb = *(const float4*)&x0[(n0 + r) * 128 + c];
                float4 o;
                float v;
                v = acc[mi * 8 + h * 4 + 0] + __ldg(&linb[c + 0]); o.x = (v > 0.f ? v : NEG * v) + xb.x;
                v = acc[mi * 8 + h * 4 + 1] + __ldg(&linb[c + 1]); o.y = (v > 0.f ? v : NEG * v) + xb.y;
                v = acc[mi * 8 + h * 4 + 2] + __ldg(&linb[c + 2]); o.z = (v > 0.f ? v : NEG * v) + xb.z;
                v = acc[mi * 8 + h * 4 + 3] + __ldg(&linb[c + 3]); o.w = (v > 0.f ? v : NEG * v) + xb.w;
                *(float4*)&out[(n0 + r) * 128 + c] = o;
            }
        }
    }
}

// ---------------- launcher ----------------
extern "C" void kernel_launch(void* const* d_in, const int* in_sizes, int n_in,
                              void* d_out, int out_size) {
    const int*   src     = (const int*)  d_in[0];
    const int*   dst     = (const int*)  d_in[1];
    const float* x0      = (const float*)d_in[2];
    const float* x       = (const float*)d_in[3];
    const float* e       = (const float*)d_in[4];
    const float* alpha   = (const float*)d_in[7];
    const float* emb     = (const float*)d_in[8];
    const float* w1      = (const float*)d_in[9];
    const float* b1      = (const float*)d_in[10];
    const float* w2      = (const float*)d_in[11];
    const float* b2      = (const float*)d_in[12];
    const float* weights = (const float*)d_in[13];
    const float* lin_w   = (const float*)d_in[14];
    const float* lin_b   = (const float*)d_in[15];
    float* out = (float*)d_out;

    cudaFuncSetAttribute(k_pred,  cudaFuncAttributeMaxDynamicSharedMemorySize, GEMM_SMEM);
    cudaFuncSetAttribute(k_final, cudaFuncAttributeMaxDynamicSharedMemorySize, GEMM_SMEM);

    const int NBLK_SCAN = (NN + 1023) / 1024;       // 98
    const int NBLK_GEMM = (NN + 127) / 128;         // 782

    k_prep<<<512, 128>>>(w1, lin_w, weights);
    k_zero<<<(NN + 255) / 256, 256>>>();
    k_deg<<<(EE + 255) / 256, 256>>>(dst);
    k_scan_block<<<NBLK_SCAN, 1024>>>();
    k_scan_top<<<1, 128>>>(NBLK_SCAN);
    k_scan_add<<<NBLK_SCAN, 1024>>>();
    k_fill<<<(EE + 255) / 256, 256>>>(src, dst);
    k_pred<<<NBLK_GEMM, 256, GEMM_SMEM>>>(x, b1, w2, b2, alpha, emb);
    k_lap1<<<(NN * 32 + 255) / 256, 256>>>();
    k_lap2<<<(NN * 32 + 255) / 256, 256>>>();
    k_final<<<NBLK_GEMM, 256, GEMM_SMEM>>>(e, x, x0, lin_b, out);
}

// round 3
// speedup vs baseline: 1.7848x; 1.7848x over previous
#include <cuda_runtime.h>
#include <cuda_fp16.h>
#include <cstdint>

#define NN 100000
#define EE 800000
#define DD 128
#define TH0 0.5f
#define TH1 0.3f
#define TH2 0.2f
#define NEG 0.01f

// smem offsets (bytes)
#define OFFA 0
#define OFFB 32768
#define OFFLP 65536                     // float2[2][128] = 2048
#define OFFPS 67584                     // float[128]
#define PRED_SMEM (OFFPS + 512)
#define FIN_SMEM  65536

// ---------------- device scratch ----------------
__device__ int   g_deg[NN];
__device__ int   g_rowptr[NN + 1];
__device__ int   g_cursor[NN];
__device__ int   g_partials[128];
__device__ int   g_blockoff[128];
__device__ float g_dinv[NN];
__device__ int   g_col[EE];
__device__ float g_xk0[NN * DD];
__device__ float g_xk1[NN * DD];
__device__ __align__(16) __half g_hih[NN * DD];        // hi as f16
__device__ __align__(16) __half g_W1h[128 * 128];      // W1 [n][k] f16
__device__ __align__(16) __half g_Bh[128 * 384];       // combined B [n][kk] f16

// ---------------- helpers ----------------
__device__ __forceinline__ uint32_t smem_u32(const void* p) {
    uint32_t a;
    asm("{ .reg .u64 t; cvta.to.shared.u64 t, %1; cvt.u32.u64 %0, t; }" : "=r"(a) : "l"(p));
    return a;
}
__device__ __forceinline__ void ldsm4(uint32_t* r, uint32_t addr) {
    asm volatile("ldmatrix.sync.aligned.m8n8.x4.shared.b16 {%0,%1,%2,%3}, [%4];"
                 : "=r"(r[0]), "=r"(r[1]), "=r"(r[2]), "=r"(r[3]) : "r"(addr));
}
__device__ __forceinline__ void mma16816(float* c, const uint32_t* a, const uint32_t* b) {
    asm volatile("mma.sync.aligned.m16n8k16.row.col.f32.f16.f16.f32 "
                 "{%0,%1,%2,%3},{%4,%5,%6,%7},{%8,%9},{%0,%1,%2,%3};"
                 : "+f"(c[0]), "+f"(c[1]), "+f"(c[2]), "+f"(c[3])
                 : "r"(a[0]), "r"(a[1]), "r"(a[2]), "r"(a[3]), "r"(b[0]), "r"(b[1]));
}
__device__ __forceinline__ uint4 pack8(float4 a, float4 b) {
    __half2 h0 = __floats2half2_rn(a.x, a.y);
    __half2 h1 = __floats2half2_rn(a.z, a.w);
    __half2 h2 = __floats2half2_rn(b.x, b.y);
    __half2 h3 = __floats2half2_rn(b.z, b.w);
    return make_uint4(*(unsigned*)&h0, *(unsigned*)&h1, *(unsigned*)&h2, *(unsigned*)&h3);
}
// smem byte address for (row, 16B-chunk) with XOR swizzle, 256B row stride
__device__ __forceinline__ int swz(int row, int chunk) {
    return row * 256 + ((chunk ^ (row & 7)) << 4);
}

// ---------------- prep: f16 operand images ----------------
__global__ void k_prep(const float* __restrict__ w1,
                       const float* __restrict__ lin_w,
                       const float* __restrict__ weights) {
    int bid = blockIdx.x, t = threadIdx.x;
    if (bid < 128) {
        g_W1h[bid * 128 + t] = __float2half_rn(w1[bid * 128 + t]);
    } else {
        int kk = bid - 128;            // 0..383
        float v;
        if (kk < 128) {
            v = lin_w[t * 256 + kk];
        } else {
            int r = kk - 128;
            float s = 0.f;
            #pragma unroll 4
            for (int o = 0; o < 128; o++)
                s = fmaf(__ldg(&weights[r * 128 + o]), __ldg(&lin_w[t * 256 + 128 + o]), s);
            v = s;
        }
        g_Bh[t * 384 + kk] = __float2half_rn(v);
    }
}

// ---------------- CSR build ----------------
__global__ void k_zero() {
    int i = blockIdx.x * blockDim.x + threadIdx.x;
    if (i < NN) g_deg[i] = 0;
}
__global__ void k_deg(const int* __restrict__ dst) {
    int i = blockIdx.x * blockDim.x + threadIdx.x;
    if (i < EE) atomicAdd(&g_deg[dst[i]], 1);
}
__global__ void k_scan_block() {
    __shared__ int s[1024];
    int i = blockIdx.x * 1024 + threadIdx.x;
    int v = (i < NN) ? g_deg[i] : 0;
    s[threadIdx.x] = v;
    __syncthreads();
    for (int off = 1; off < 1024; off <<= 1) {
        int t = (threadIdx.x >= off) ? s[threadIdx.x - off] : 0;
        __syncthreads();
        s[threadIdx.x] += t;
        __syncthreads();
    }
    if (i < NN) g_rowptr[i] = s[threadIdx.x] - v;
    if (threadIdx.x == 1023) g_partials[blockIdx.x] = s[1023];
}
__global__ void k_scan_top(int nblk) {
    __shared__ int s[128];
    int t = threadIdx.x;
    int v = (t < nblk) ? g_partials[t] : 0;
    s[t] = v;
    __syncthreads();
    for (int off = 1; off < 128; off <<= 1) {
        int u = (t >= off) ? s[t - off] : 0;
        __syncthreads();
        s[t] += u;
        __syncthreads();
    }
    g_blockoff[t] = s[t] - v;
}
__global__ void k_scan_add() {
    int i = blockIdx.x * 1024 + threadIdx.x;
    if (i < NN) {
        int r = g_rowptr[i] + g_blockoff[blockIdx.x];
        g_rowptr[i] = r;
        g_cursor[i] = r;
        int d = g_deg[i];
        g_dinv[i] = rsqrtf((float)(d > 0 ? d : 1));
        if (i == NN - 1) g_rowptr[NN] = EE;
    }
}
__global__ void k_fill(const int* __restrict__ src, const int* __restrict__ dst) {
    int i = blockIdx.x * blockDim.x + threadIdx.x;
    if (i < EE) {
        int p = atomicAdd(&g_cursor[dst[i]], 1);
        g_col[p] = src[i];
    }
}

// ---------------- predictor: HMMA GEMM + softmax head + xk0 ----------------
__global__ __launch_bounds__(256)
void k_pred(const float* __restrict__ x, const float* __restrict__ b1,
            const float* __restrict__ w2, const float* __restrict__ b2,
            const float* __restrict__ alpha, const float* __restrict__ emb) {
    extern __shared__ __align__(16) unsigned char sm[];
    uint32_t sbase = smem_u32(sm);
    const int tid = threadIdx.x, lane = tid & 31, wid = tid >> 5;
    const int n0 = blockIdx.x * 128;
    const int rows = min(128, NN - n0);

    // stage A = f16(x tile) swizzled
    for (int i = tid; i < 2048; i += 256) {
        int r = i >> 4, c = i & 15;
        float4 va = make_float4(0.f, 0.f, 0.f, 0.f), vb = va;
        if (r < rows) {
            va = *(const float4*)&x[(n0 + r) * 128 + c * 8];
            vb = *(const float4*)&x[(n0 + r) * 128 + c * 8 + 4];
        }
        *(uint4*)(sm + OFFA + swz(r, c)) = pack8(va, vb);
    }
    // stage B = W1h swizzled
    for (int i = tid; i < 2048; i += 256) {
        int r = i >> 4, c = i & 15;
        *(uint4*)(sm + OFFB + swz(r, c)) = ((const uint4*)g_W1h)[i];
    }
    __syncthreads();

    // warp tile: 2 m-tiles(16) x 8 n-tiles(8)
    const int wm = wid & 3, wn = wid >> 2;
    const int m_base = wm * 32, n_base = wn * 64;
    const int rA0 = m_base + (lane & 15), rA1 = rA0 + 16;
    const int chA = lane >> 4;                 // +0/+1 chunk
    int rB[4];
    #pragma unroll
    for (int np = 0; np < 4; np++)
        rB[np] = n_base + np * 16 + (lane & 7) + ((lane & 16) >> 1);
    const int chB = (lane >> 3) & 1;

    float acc[2][8][4];
    #pragma unroll
    for (int mt = 0; mt < 2; mt++)
        #pragma unroll
        for (int nt = 0; nt < 8; nt++)
            #pragma unroll
            for (int q = 0; q < 4; q++) acc[mt][nt][q] = 0.f;

    #pragma unroll
    for (int ks = 0; ks < 8; ks++) {
        uint32_t af[2][4], bf[4][4];
        ldsm4(af[0], sbase + OFFA + swz(rA0, 2 * ks + chA));
        ldsm4(af[1], sbase + OFFA + swz(rA1, 2 * ks + chA));
        #pragma unroll
        for (int np = 0; np < 4; np++)
            ldsm4(bf[np], sbase + OFFB + swz(rB[np], 2 * ks + chB));
        #pragma unroll
        for (int mt = 0; mt < 2; mt++)
            #pragma unroll
            for (int nt = 0; nt < 8; nt++)
                mma16816(acc[mt][nt], af[mt], &bf[nt >> 1][(nt & 1) * 2]);
    }
    __syncthreads();

    // epilogue: h=relu(acc+b1); logits partials per owned row
    float lp0[2][2] = {{0.f, 0.f}, {0.f, 0.f}};
    float lp1[2][2] = {{0.f, 0.f}, {0.f, 0.f}};
    #pragma unroll
    for (int nt = 0; nt < 8; nt++) {
        int col = n_base + nt * 8 + 2 * (lane & 3);
        float b1a = __ldg(&b1[col]), b1b = __ldg(&b1[col + 1]);
        float wa0 = __ldg(&w2[col]), wb0 = __ldg(&w2[col + 1]);
        float wa1 = __ldg(&w2[128 + col]), wb1 = __ldg(&w2[128 + col + 1]);
        #pragma unroll
        for (int mt = 0; mt < 2; mt++)
            #pragma unroll
            for (int rh = 0; rh < 2; rh++) {
                float h0 = fmaxf(acc[mt][nt][2 * rh] + b1a, 0.f);
                float h1 = fmaxf(acc[mt][nt][2 * rh + 1] + b1b, 0.f);
                lp0[mt][rh] += h0 * wa0 + h1 * wb0;
                lp1[mt][rh] += h0 * wa1 + h1 * wb1;
            }
    }
    float2* Lp = (float2*)(sm + OFFLP);
    #pragma unroll
    for (int mt = 0; mt < 2; mt++)
        #pragma unroll
        for (int rh = 0; rh < 2; rh++) {
            float a0 = lp0[mt][rh], a1 = lp1[mt][rh];
            a0 += __shfl_xor_sync(0xFFFFFFFF, a0, 1);
            a0 += __shfl_xor_sync(0xFFFFFFFF, a0, 2);
            a1 += __shfl_xor_sync(0xFFFFFFFF, a1, 1);
            a1 += __shfl_xor_sync(0xFFFFFFFF, a1, 2);
            if ((lane & 3) == 0) {
                int row = m_base + mt * 16 + (lane >> 2) + rh * 8;
                Lp[wn * 128 + row] = make_float2(a0, a1);
            }
        }
    __syncthreads();

    float* Ps = (float*)(sm + OFFPS);
    if (tid < 128) {
        float2 u = Lp[tid], v = Lp[128 + tid];
        float l0 = u.x + v.x + __ldg(&b2[0]);
        float l1 = u.y + v.y + __ldg(&b2[1]);
        Ps[tid] = 1.f / (1.f + expf(l0 - l1));
    }
    __syncthreads();

    const float al = __ldg(&alpha[0]);
    for (int idx = tid; idx < 128 * 32; idx += 256) {
        int m = idx >> 5, cq = (idx & 31) * 4;
        if (m < rows) {
            float p = Ps[m];
            float4 xv = *(const float4*)&x[(n0 + m) * 128 + cq];
            float4 e0 = *(const float4*)&emb[cq];
            float4 e1 = *(const float4*)&emb[128 + cq];
            float4 o;
            o.x = xv.x + al * ((1.f - p) * e0.x + p * e1.x);
            o.y = xv.y + al * ((1.f - p) * e0.y + p * e1.y);
            o.z = xv.z + al * ((1.f - p) * e0.z + p * e1.z);
            o.w = xv.w + al * ((1.f - p) * e0.w + p * e1.w);
            *(float4*)&g_xk0[(n0 + m) * 128 + cq] = o;
        }
    }
}

// ---------------- Laplacian passes ----------------
__global__ __launch_bounds__(256)
void k_lap1() {
    int gw = (blockIdx.x * blockDim.x + threadIdx.x) >> 5;
    if (gw >= NN) return;
    int lane = threadIdx.x & 31;
    const float4* xin = (const float4*)g_xk0;
    int beg = g_rowptr[gw], end = g_rowptr[gw + 1];
    float4 acc = make_float4(0.f, 0.f, 0.f, 0.f);
    for (int ei = beg; ei < end; ei++) {
        int u = __ldg(&g_col[ei]);
        float du = __ldg(&g_dinv[u]);
        float4 xu = __ldg(&xin[u * 32 + lane]);
        acc.x = fmaf(xu.x, du, acc.x); acc.y = fmaf(xu.y, du, acc.y);
        acc.z = fmaf(xu.z, du, acc.z); acc.w = fmaf(xu.w, du, acc.w);
    }
    float dv = g_dinv[gw];
    float4 xv = xin[gw * 32 + lane];
    float4 r;
    r.x = xv.x - acc.x * dv; r.y = xv.y - acc.y * dv;
    r.z = xv.z - acc.z * dv; r.w = xv.w - acc.w * dv;
    ((float4*)g_xk1)[gw * 32 + lane] = r;
}
__global__ __launch_bounds__(256)
void k_lap2() {
    int gw = (blockIdx.x * blockDim.x + threadIdx.x) >> 5;
    if (gw >= NN) return;
    int lane = threadIdx.x & 31;
    const float4* x1 = (const float4*)g_xk1;
    int beg = g_rowptr[gw], end = g_rowptr[gw + 1];
    float4 acc = make_float4(0.f, 0.f, 0.f, 0.f);
    for (int ei = beg; ei < end; ei++) {
        int u = __ldg(&g_col[ei]);
        float du = __ldg(&g_dinv[u]);
        float4 xu = __ldg(&x1[u * 32 + lane]);
        acc.x = fmaf(xu.x, du, acc.x); acc.y = fmaf(xu.y, du, acc.y);
        acc.z = fmaf(xu.z, du, acc.z); acc.w = fmaf(xu.w, du, acc.w);
    }
    float dv = g_dinv[gw];
    float4 v0 = ((const float4*)g_xk0)[gw * 32 + lane];
    float4 v1 = x1[gw * 32 + lane];
    const float c1 = TH1 + TH2;
    float4 r;
    r.x = TH0 * v0.x + c1 * v1.x - TH2 * (acc.x * dv);
    r.y = TH0 * v0.y + c1 * v1.y - TH2 * (acc.y * dv);
    r.z = TH0 * v0.z + c1 * v1.z - TH2 * (acc.z * dv);
    r.w = TH0 * v0.w + c1 * v1.w - TH2 * (acc.w * dv);
    __half2 a = __floats2half2_rn(r.x, r.y);
    __half2 b = __floats2half2_rn(r.z, r.w);
    ((uint2*)g_hih)[gw * 32 + lane] = make_uint2(*(unsigned*)&a, *(unsigned*)&b);
}

// ---------------- final: HMMA GEMM (K=384, 3 segs) + leaky + x0 ----------------
__global__ __launch_bounds__(256)
void k_final(const float* __restrict__ e, const float* __restrict__ x,
             const float* __restrict__ x0, const float* __restrict__ linb,
             float* __restrict__ out) {
    extern __shared__ __align__(16) unsigned char sm[];
    uint32_t sbase = smem_u32(sm);
    const int tid = threadIdx.x, lane = tid & 31, wid = tid >> 5;
    const int n0 = blockIdx.x * 128;
    const int rows = min(128, NN - n0);

    const int wm = wid & 3, wn = wid >> 2;
    const int m_base = wm * 32, n_base = wn * 64;
    const int rA0 = m_base + (lane & 15), rA1 = rA0 + 16;
    const int chA = lane >> 4;
    int rB[4];
    #pragma unroll
    for (int np = 0; np < 4; np++)
        rB[np] = n_base + np * 16 + (lane & 7) + ((lane & 16) >> 1);
    const int chB = (lane >> 3) & 1;

    float acc[2][8][4];
    #pragma unroll
    for (int mt = 0; mt < 2; mt++)
        #pragma unroll
        for (int nt = 0; nt < 8; nt++)
            #pragma unroll
            for (int q = 0; q < 4; q++) acc[mt][nt][q] = 0.f;

    for (int s = 0; s < 3; s++) {
        // stage A segment
        if (s == 1) {
            for (int i = tid; i < 2048; i += 256) {
                int r = i >> 4, c = i & 15;
                uint4 v = make_uint4(0u, 0u, 0u, 0u);
                if (r < rows) v = ((const uint4*)g_hih)[(n0 + r) * 16 + c];
                *(uint4*)(sm + OFFA + swz(r, c)) = v;
            }
        } else {
            const float* srcm = (s == 0) ? e : x;
            for (int i = tid; i < 2048; i += 256) {
                int r = i >> 4, c = i & 15;
                float4 va = make_float4(0.f, 0.f, 0.f, 0.f), vb = va;
                if (r < rows) {
                    va = *(const float4*)&srcm[(n0 + r) * 128 + c * 8];
                    vb = *(const float4*)&srcm[(n0 + r) * 128 + c * 8 + 4];
                }
                *(uint4*)(sm + OFFA + swz(r, c)) = pack8(va, vb);
            }
        }
        // stage B segment (cols kk in [128s, 128s+128))
        for (int i = tid; i < 2048; i += 256) {
            int r = i >> 4, c = i & 15;
            *(uint4*)(sm + OFFB + swz(r, c)) = ((const uint4*)g_Bh)[r * 48 + s * 16 + c];
        }
        __syncthreads();

        #pragma unroll
        for (int ks = 0; ks < 8; ks++) {
            uint32_t af[2][4], bf[4][4];
            ldsm4(af[0], sbase + OFFA + swz(rA0, 2 * ks + chA));
            ldsm4(af[1], sbase + OFFA + swz(rA1, 2 * ks + chA));
            #pragma unroll
            for (int np = 0; np < 4; np++)
                ldsm4(bf[np], sbase + OFFB + swz(rB[np], 2 * ks + chB));
            #pragma unroll
            for (int mt = 0; mt < 2; mt++)
                #pragma unroll
                for (int nt = 0; nt < 8; nt++)
                    mma16816(acc[mt][nt], af[mt], &bf[nt >> 1][(nt & 1) * 2]);
        }
        __syncthreads();
    }

    // epilogue: leaky(acc + lin_b) + x0, direct float2 stores
    #pragma unroll
    for (int mt = 0; mt < 2; mt++)
        #pragma unroll
        for (int rh = 0; rh < 2; rh++) {
            int row = m_base + mt * 16 + (lane >> 2) + rh * 8;
            if (row < rows) {
                int m = n0 + row;
                #pragma unroll
                for (int nt = 0; nt < 8; nt++) {
                    int col = n_base + nt * 8 + 2 * (lane & 3);
                    float v0 = acc[mt][nt][2 * rh]     + __ldg(&linb[col]);
                    float v1 = acc[mt][nt][2 * rh + 1] + __ldg(&linb[col + 1]);
                    v0 = v0 > 0.f ? v0 : NEG * v0;
                    v1 = v1 > 0.f ? v1 : NEG * v1;
                    float2 xb = *(const float2*)&x0[m * 128 + col];
                    *(float2*)&out[m * 128 + col] = make_float2(v0 + xb.x, v1 + xb.y);
                }
            }
        }
}

// ---------------- launcher ----------------
extern "C" void kernel_launch(void* const* d_in, const int* in_sizes, int n_in,
                              void* d_out, int out_size) {
    const int*   src     = (const int*)  d_in[0];
    const int*   dst     = (const int*)  d_in[1];
    const float* x0      = (const float*)d_in[2];
    const float* x       = (const float*)d_in[3];
    const float* e       = (const float*)d_in[4];
    const float* alpha   = (const float*)d_in[7];
    const float* emb     = (const float*)d_in[8];
    const float* w1      = (const float*)d_in[9];
    const float* b1      = (const float*)d_in[10];
    const float* w2      = (const float*)d_in[11];
    const float* b2      = (const float*)d_in[12];
    const float* weights = (const float*)d_in[13];
    const float* lin_w   = (const float*)d_in[14];
    const float* lin_b   = (const float*)d_in[15];
    float* out = (float*)d_out;

    cudaFuncSetAttribute(k_pred,  cudaFuncAttributeMaxDynamicSharedMemorySize, PRED_SMEM);
    cudaFuncSetAttribute(k_final, cudaFuncAttributeMaxDynamicSharedMemorySize, FIN_SMEM);

    const int NBLK_SCAN = (NN + 1023) / 1024;
    const int NBLK_GEMM = (NN + 127) / 128;

    k_prep<<<512, 128>>>(w1, lin_w, weights);
    k_zero<<<(NN + 255) / 256, 256>>>();
    k_deg<<<(EE + 255) / 256, 256>>>(dst);
    k_scan_block<<<NBLK_SCAN, 1024>>>();
    k_scan_top<<<1, 128>>>(NBLK_SCAN);
    k_scan_add<<<NBLK_SCAN, 1024>>>();
    k_fill<<<(EE + 255) / 256, 256>>>(src, dst);
    k_pred<<<NBLK_GEMM, 256, PRED_SMEM>>>(x, b1, w2, b2, alpha, emb);
    k_lap1<<<(NN * 32 + 255) / 256, 256>>>();
    k_lap2<<<(NN * 32 + 255) / 256, 256>>>();
    k_final<<<NBLK_GEMM, 256, FIN_SMEM>>>(e, x, x0, lin_b, out);
}

// round 4
// speedup vs baseline: 2.3772x; 1.3319x over previous
#include <cuda_runtime.h>
#include <cuda_fp16.h>
#include <cstdint>

#define NN 100000
#define EE 800000
#define DD 128
#define TH0 0.5f
#define TH1 0.3f
#define TH2 0.2f
#define NEG 0.01f

// smem offsets (bytes)
#define OFFA 0
#define OFFB 32768
#define OFFLP 65536                     // float2[2][128] = 2048
#define OFFPS 67584                     // float[128]
#define PRED_SMEM (OFFPS + 512)
#define FIN_SMEM  65536

// ---------------- device scratch ----------------
__device__ int   g_deg[NN];
__device__ int   g_rowptr[NN + 1];
__device__ int   g_cursor[NN];
__device__ int   g_partials[128];
__device__ float g_dinv[NN];
__device__ int   g_col[EE];
__device__ float g_xk0[NN * DD];
__device__ float g_xk1[NN * DD];
__device__ __align__(16) __half g_xs0h[NN * DD];       // dinv*xk0 as f16 (gather operand)
__device__ __align__(16) __half g_xs1h[NN * DD];       // dinv*xk1 as f16 (gather operand)
__device__ __align__(16) __half g_hih[NN * DD];        // hi as f16
__device__ __align__(16) __half g_W1h[128 * 128];      // W1 [n][k] f16
__device__ __align__(16) __half g_Bh[128 * 384];       // combined B [n][kk] f16

// ---------------- helpers ----------------
__device__ __forceinline__ uint32_t smem_u32(const void* p) {
    uint32_t a;
    asm("{ .reg .u64 t; cvta.to.shared.u64 t, %1; cvt.u32.u64 %0, t; }" : "=r"(a) : "l"(p));
    return a;
}
__device__ __forceinline__ void ldsm4(uint32_t* r, uint32_t addr) {
    asm volatile("ldmatrix.sync.aligned.m8n8.x4.shared.b16 {%0,%1,%2,%3}, [%4];"
                 : "=r"(r[0]), "=r"(r[1]), "=r"(r[2]), "=r"(r[3]) : "r"(addr));
}
__device__ __forceinline__ void mma16816(float* c, const uint32_t* a, const uint32_t* b) {
    asm volatile("mma.sync.aligned.m16n8k16.row.col.f32.f16.f16.f32 "
                 "{%0,%1,%2,%3},{%4,%5,%6,%7},{%8,%9},{%0,%1,%2,%3};"
                 : "+f"(c[0]), "+f"(c[1]), "+f"(c[2]), "+f"(c[3])
                 : "r"(a[0]), "r"(a[1]), "r"(a[2]), "r"(a[3]), "r"(b[0]), "r"(b[1]));
}
__device__ __forceinline__ uint4 pack8(float4 a, float4 b) {
    __half2 h0 = __floats2half2_rn(a.x, a.y);
    __half2 h1 = __floats2half2_rn(a.z, a.w);
    __half2 h2 = __floats2half2_rn(b.x, b.y);
    __half2 h3 = __floats2half2_rn(b.z, b.w);
    return make_uint4(*(unsigned*)&h0, *(unsigned*)&h1, *(unsigned*)&h2, *(unsigned*)&h3);
}
__device__ __forceinline__ uint2 pack4(float4 a) {
    __half2 h0 = __floats2half2_rn(a.x, a.y);
    __half2 h1 = __floats2half2_rn(a.z, a.w);
    return make_uint2(*(unsigned*)&h0, *(unsigned*)&h1);
}
// smem byte address for (row, 16B-chunk) with XOR swizzle, 256B row stride
__device__ __forceinline__ int swz(int row, int chunk) {
    return row * 256 + ((chunk ^ (row & 7)) << 4);
}

// ---------------- prep: f16 operand images ----------------
__global__ void k_prep(const float* __restrict__ w1,
                       const float* __restrict__ lin_w,
                       const float* __restrict__ weights) {
    int bid = blockIdx.x, t = threadIdx.x;
    if (bid < 128) {
        g_W1h[bid * 128 + t] = __float2half_rn(w1[bid * 128 + t]);
    } else {
        int kk = bid - 128;            // 0..383
        float v;
        if (kk < 128) {
            v = lin_w[t * 256 + kk];
        } else {
            int r = kk - 128;
            float s = 0.f;
            #pragma unroll 4
            for (int o = 0; o < 128; o++)
                s = fmaf(__ldg(&weights[r * 128 + o]), __ldg(&lin_w[t * 256 + 128 + o]), s);
            v = s;
        }
        g_Bh[t * 384 + kk] = __float2half_rn(v);
    }
}

// ---------------- CSR build ----------------
__global__ void k_zero() {
    int i = blockIdx.x * blockDim.x + threadIdx.x;
    if (i < NN) g_deg[i] = 0;
}
__global__ void k_deg(const int* __restrict__ dst) {
    int i = blockIdx.x * blockDim.x + threadIdx.x;
    if (i < EE) atomicAdd(&g_deg[dst[i]], 1);
}
__global__ void k_scan_block() {
    __shared__ int s[1024];
    int i = blockIdx.x * 1024 + threadIdx.x;
    int v = (i < NN) ? g_deg[i] : 0;
    s[threadIdx.x] = v;
    __syncthreads();
    for (int off = 1; off < 1024; off <<= 1) {
        int t = (threadIdx.x >= off) ? s[threadIdx.x - off] : 0;
        __syncthreads();
        s[threadIdx.x] += t;
        __syncthreads();
    }
    if (i < NN) g_rowptr[i] = s[threadIdx.x] - v;
    if (threadIdx.x == 1023) g_partials[blockIdx.x] = s[1023];
}
// adds block offset (scans partials locally), sets cursor+dinv
__global__ void k_scan_add() {
    __shared__ int soff;
    if (threadIdx.x == 0) {
        int acc = 0;
        for (int b = 0; b < (int)blockIdx.x; b++) acc += g_partials[b];
        soff = acc;
    }
    __syncthreads();
    int i = blockIdx.x * 1024 + threadIdx.x;
    if (i < NN) {
        int r = g_rowptr[i] + soff;
        g_rowptr[i] = r;
        g_cursor[i] = r;
        int d = g_deg[i];
        g_dinv[i] = rsqrtf((float)(d > 0 ? d : 1));
        if (i == NN - 1) g_rowptr[NN] = EE;
    }
}
__global__ void k_fill(const int* __restrict__ src, const int* __restrict__ dst) {
    int i = blockIdx.x * blockDim.x + threadIdx.x;
    if (i < EE) {
        int p = atomicAdd(&g_cursor[dst[i]], 1);
        g_col[p] = src[i];
    }
}

// ---------------- predictor: HMMA GEMM + softmax head + xk0 (+xs0h) ----------------
__global__ __launch_bounds__(256)
void k_pred(const float* __restrict__ x, const float* __restrict__ b1,
            const float* __restrict__ w2, const float* __restrict__ b2,
            const float* __restrict__ alpha, const float* __restrict__ emb) {
    extern __shared__ __align__(16) unsigned char sm[];
    uint32_t sbase = smem_u32(sm);
    const int tid = threadIdx.x, lane = tid & 31, wid = tid >> 5;
    const int n0 = blockIdx.x * 128;
    const int rows = min(128, NN - n0);

    // stage A = f16(x tile) swizzled
    for (int i = tid; i < 2048; i += 256) {
        int r = i >> 4, c = i & 15;
        float4 va = make_float4(0.f, 0.f, 0.f, 0.f), vb = va;
        if (r < rows) {
            va = *(const float4*)&x[(n0 + r) * 128 + c * 8];
            vb = *(const float4*)&x[(n0 + r) * 128 + c * 8 + 4];
        }
        *(uint4*)(sm + OFFA + swz(r, c)) = pack8(va, vb);
    }
    // stage B = W1h swizzled
    for (int i = tid; i < 2048; i += 256) {
        int r = i >> 4, c = i & 15;
        *(uint4*)(sm + OFFB + swz(r, c)) = ((const uint4*)g_W1h)[i];
    }
    __syncthreads();

    const int wm = wid & 3, wn = wid >> 2;
    const int m_base = wm * 32, n_base = wn * 64;
    const int rA0 = m_base + (lane & 15), rA1 = rA0 + 16;
    const int chA = lane >> 4;
    int rB[4];
    #pragma unroll
    for (int np = 0; np < 4; np++)
        rB[np] = n_base + np * 16 + (lane & 7) + ((lane & 16) >> 1);
    const int chB = (lane >> 3) & 1;

    float acc[2][8][4];
    #pragma unroll
    for (int mt = 0; mt < 2; mt++)
        #pragma unroll
        for (int nt = 0; nt < 8; nt++)
            #pragma unroll
            for (int q = 0; q < 4; q++) acc[mt][nt][q] = 0.f;

    #pragma unroll
    for (int ks = 0; ks < 8; ks++) {
        uint32_t af[2][4], bf[4][4];
        ldsm4(af[0], sbase + OFFA + swz(rA0, 2 * ks + chA));
        ldsm4(af[1], sbase + OFFA + swz(rA1, 2 * ks + chA));
        #pragma unroll
        for (int np = 0; np < 4; np++)
            ldsm4(bf[np], sbase + OFFB + swz(rB[np], 2 * ks + chB));
        #pragma unroll
        for (int mt = 0; mt < 2; mt++)
            #pragma unroll
            for (int nt = 0; nt < 8; nt++)
                mma16816(acc[mt][nt], af[mt], &bf[nt >> 1][(nt & 1) * 2]);
    }
    __syncthreads();

    // epilogue: h=relu(acc+b1); logits partials per owned row
    float lp0[2][2] = {{0.f, 0.f}, {0.f, 0.f}};
    float lp1[2][2] = {{0.f, 0.f}, {0.f, 0.f}};
    #pragma unroll
    for (int nt = 0; nt < 8; nt++) {
        int col = n_base + nt * 8 + 2 * (lane & 3);
        float b1a = __ldg(&b1[col]), b1b = __ldg(&b1[col + 1]);
        float wa0 = __ldg(&w2[col]), wb0 = __ldg(&w2[col + 1]);
        float wa1 = __ldg(&w2[128 + col]), wb1 = __ldg(&w2[128 + col + 1]);
        #pragma unroll
        for (int mt = 0; mt < 2; mt++)
            #pragma unroll
            for (int rh = 0; rh < 2; rh++) {
                float h0 = fmaxf(acc[mt][nt][2 * rh] + b1a, 0.f);
                float h1 = fmaxf(acc[mt][nt][2 * rh + 1] + b1b, 0.f);
                lp0[mt][rh] += h0 * wa0 + h1 * wb0;
                lp1[mt][rh] += h0 * wa1 + h1 * wb1;
            }
    }
    float2* Lp = (float2*)(sm + OFFLP);
    #pragma unroll
    for (int mt = 0; mt < 2; mt++)
        #pragma unroll
        for (int rh = 0; rh < 2; rh++) {
            float a0 = lp0[mt][rh], a1 = lp1[mt][rh];
            a0 += __shfl_xor_sync(0xFFFFFFFF, a0, 1);
            a0 += __shfl_xor_sync(0xFFFFFFFF, a0, 2);
            a1 += __shfl_xor_sync(0xFFFFFFFF, a1, 1);
            a1 += __shfl_xor_sync(0xFFFFFFFF, a1, 2);
            if ((lane & 3) == 0) {
                int row = m_base + mt * 16 + (lane >> 2) + rh * 8;
                Lp[wn * 128 + row] = make_float2(a0, a1);
            }
        }
    __syncthreads();

    float* Ps = (float*)(sm + OFFPS);
    if (tid < 128) {
        float2 u = Lp[tid], v = Lp[128 + tid];
        float l0 = u.x + v.x + __ldg(&b2[0]);
        float l1 = u.y + v.y + __ldg(&b2[1]);
        Ps[tid] = 1.f / (1.f + expf(l0 - l1));
    }
    __syncthreads();

    const float al = __ldg(&alpha[0]);
    for (int idx = tid; idx < 128 * 32; idx += 256) {
        int m = idx >> 5, cq = (idx & 31) * 4;
        if (m < rows) {
            float p = Ps[m];
            float dv = __ldg(&g_dinv[n0 + m]);
            float4 xv = *(const float4*)&x[(n0 + m) * 128 + cq];
            float4 e0 = *(const float4*)&emb[cq];
            float4 e1 = *(const float4*)&emb[128 + cq];
            float4 o;
            o.x = xv.x + al * ((1.f - p) * e0.x + p * e1.x);
            o.y = xv.y + al * ((1.f - p) * e0.y + p * e1.y);
            o.z = xv.z + al * ((1.f - p) * e0.z + p * e1.z);
            o.w = xv.w + al * ((1.f - p) * e0.w + p * e1.w);
            *(float4*)&g_xk0[(n0 + m) * 128 + cq] = o;
            float4 s = make_float4(o.x * dv, o.y * dv, o.z * dv, o.w * dv);
            ((uint2*)g_xs0h)[(n0 + m) * 32 + (idx & 31)] = pack4(s);
        }
    }
}

// ---------------- Laplacian passes (f16 gather, dinv pre-applied) ----------------
__global__ __launch_bounds__(256)
void k_lap1() {
    int gw = (blockIdx.x * blockDim.x + threadIdx.x) >> 5;
    if (gw >= NN) return;
    int lane = threadIdx.x & 31;
    const uint2* xs = (const uint2*)g_xs0h;
    int beg = g_rowptr[gw], end = g_rowptr[gw + 1];
    float4 acc = make_float4(0.f, 0.f, 0.f, 0.f);
    #pragma unroll 4
    for (int ei = beg; ei < end; ei++) {
        int u = __ldg(&g_col[ei]);
        uint2 hv = __ldg(&xs[u * 32 + lane]);
        float2 lo = __half22float2(*(__half2*)&hv.x);
        float2 hi = __half22float2(*(__half2*)&hv.y);
        acc.x += lo.x; acc.y += lo.y; acc.z += hi.x; acc.w += hi.y;
    }
    float dv = g_dinv[gw];
    float4 xv = ((const float4*)g_xk0)[gw * 32 + lane];
    float4 r;
    r.x = xv.x - acc.x * dv; r.y = xv.y - acc.y * dv;
    r.z = xv.z - acc.z * dv; r.w = xv.w - acc.w * dv;
    ((float4*)g_xk1)[gw * 32 + lane] = r;
    float4 s = make_float4(r.x * dv, r.y * dv, r.z * dv, r.w * dv);
    ((uint2*)g_xs1h)[gw * 32 + lane] = pack4(s);
}
__global__ __launch_bounds__(256)
void k_lap2() {
    int gw = (blockIdx.x * blockDim.x + threadIdx.x) >> 5;
    if (gw >= NN) return;
    int lane = threadIdx.x & 31;
    const uint2* xs = (const uint2*)g_xs1h;
    int beg = g_rowptr[gw], end = g_rowptr[gw + 1];
    float4 acc = make_float4(0.f, 0.f, 0.f, 0.f);
    #pragma unroll 4
    for (int ei = beg; ei < end; ei++) {
        int u = __ldg(&g_col[ei]);
        uint2 hv = __ldg(&xs[u * 32 + lane]);
        float2 lo = __half22float2(*(__half2*)&hv.x);
        float2 hi = __half22float2(*(__half2*)&hv.y);
        acc.x += lo.x; acc.y += lo.y; acc.z += hi.x; acc.w += hi.y;
    }
    float dv = g_dinv[gw];
    float4 v0 = ((const float4*)g_xk0)[gw * 32 + lane];
    float4 v1 = ((const float4*)g_xk1)[gw * 32 + lane];
    const float c1 = TH1 + TH2;
    float4 r;
    r.x = TH0 * v0.x + c1 * v1.x - TH2 * (acc.x * dv);
    r.y = TH0 * v0.y + c1 * v1.y - TH2 * (acc.y * dv);
    r.z = TH0 * v0.z + c1 * v1.z - TH2 * (acc.z * dv);
    r.w = TH0 * v0.w + c1 * v1.w - TH2 * (acc.w * dv);
    ((uint2*)g_hih)[gw * 32 + lane] = pack4(r);
}

// ---------------- final: HMMA GEMM (K=384, 3 segs) + leaky + x0 ----------------
__global__ __launch_bounds__(256)
void k_final(const float* __restrict__ e, const float* __restrict__ x,
             const float* __restrict__ x0, const float* __restrict__ linb,
             float* __restrict__ out) {
    extern __shared__ __align__(16) unsigned char sm[];
    uint32_t sbase = smem_u32(sm);
    const int tid = threadIdx.x, lane = tid & 31, wid = tid >> 5;
    const int n0 = blockIdx.x * 128;
    const int rows = min(128, NN - n0);

    const int wm = wid & 3, wn = wid >> 2;
    const int m_base = wm * 32, n_base = wn * 64;
    const int rA0 = m_base + (lane & 15), rA1 = rA0 + 16;
    const int chA = lane >> 4;
    int rB[4];
    #pragma unroll
    for (int np = 0; np < 4; np++)
        rB[np] = n_base + np * 16 + (lane & 7) + ((lane & 16) >> 1);
    const int chB = (lane >> 3) & 1;

    float acc[2][8][4];
    #pragma unroll
    for (int mt = 0; mt < 2; mt++)
        #pragma unroll
        for (int nt = 0; nt < 8; nt++)
            #pragma unroll
            for (int q = 0; q < 4; q++) acc[mt][nt][q] = 0.f;

    for (int s = 0; s < 3; s++) {
        if (s == 1) {
            for (int i = tid; i < 2048; i += 256) {
                int r = i >> 4, c = i & 15;
                uint4 v = make_uint4(0u, 0u, 0u, 0u);
                if (r < rows) v = ((const uint4*)g_hih)[(n0 + r) * 16 + c];
                *(uint4*)(sm + OFFA + swz(r, c)) = v;
            }
        } else {
            const float* srcm = (s == 0) ? e : x;
            for (int i = tid; i < 2048; i += 256) {
                int r = i >> 4, c = i & 15;
                float4 va = make_float4(0.f, 0.f, 0.f, 0.f), vb = va;
                if (r < rows) {
                    va = *(const float4*)&srcm[(n0 + r) * 128 + c * 8];
                    vb = *(const float4*)&srcm[(n0 + r) * 128 + c * 8 + 4];
                }
                *(uint4*)(sm + OFFA + swz(r, c)) = pack8(va, vb);
            }
        }
        for (int i = tid; i < 2048; i += 256) {
            int r = i >> 4, c = i & 15;
            *(uint4*)(sm + OFFB + swz(r, c)) = ((const uint4*)g_Bh)[r * 48 + s * 16 + c];
        }
        __syncthreads();

        #pragma unroll
        for (int ks = 0; ks < 8; ks++) {
            uint32_t af[2][4], bf[4][4];
            ldsm4(af[0], sbase + OFFA + swz(rA0, 2 * ks + chA));
            ldsm4(af[1], sbase + OFFA + swz(rA1, 2 * ks + chA));
            #pragma unroll
            for (int np = 0; np < 4; np++)
                ldsm4(bf[np], sbase + OFFB + swz(rB[np], 2 * ks + chB));
            #pragma unroll
            for (int mt = 0; mt < 2; mt++)
                #pragma unroll
                for (int nt = 0; nt < 8; nt++)
                    mma16816(acc[mt][nt], af[mt], &bf[nt >> 1][(nt & 1) * 2]);
        }
        __syncthreads();
    }

    #pragma unroll
    for (int mt = 0; mt < 2; mt++)
        #pragma unroll
        for (int rh = 0; rh < 2; rh++) {
            int row = m_base + mt * 16 + (lane >> 2) + rh * 8;
            if (row < rows) {
                int m = n0 + row;
                #pragma unroll
                for (int nt = 0; nt < 8; nt++) {
                    int col = n_base + nt * 8 + 2 * (lane & 3);
                    float v0 = acc[mt][nt][2 * rh]     + __ldg(&linb[col]);
                    float v1 = acc[mt][nt][2 * rh + 1] + __ldg(&linb[col + 1]);
                    v0 = v0 > 0.f ? v0 : NEG * v0;
                    v1 = v1 > 0.f ? v1 : NEG * v1;
                    float2 xb = *(const float2*)&x0[m * 128 + col];
                    *(float2*)&out[m * 128 + col] = make_float2(v0 + xb.x, v1 + xb.y);
                }
            }
        }
}

// ---------------- launcher ----------------
extern "C" void kernel_launch(void* const* d_in, const int* in_sizes, int n_in,
                              void* d_out, int out_size) {
    const int*   src     = (const int*)  d_in[0];
    const int*   dst     = (const int*)  d_in[1];
    const float* x0      = (const float*)d_in[2];
    const float* x       = (const float*)d_in[3];
    const float* e       = (const float*)d_in[4];
    const float* alpha   = (const float*)d_in[7];
    const float* emb     = (const float*)d_in[8];
    const float* w1      = (const float*)d_in[9];
    const float* b1      = (const float*)d_in[10];
    const float* w2      = (const float*)d_in[11];
    const float* b2      = (const float*)d_in[12];
    const float* weights = (const float*)d_in[13];
    const float* lin_w   = (const float*)d_in[14];
    const float* lin_b   = (const float*)d_in[15];
    float* out = (float*)d_out;

    cudaFuncSetAttribute(k_pred,  cudaFuncAttributeMaxDynamicSharedMemorySize, PRED_SMEM);
    cudaFuncSetAttribute(k_final, cudaFuncAttributeMaxDynamicSharedMemorySize, FIN_SMEM);

    const int NBLK_SCAN = (NN + 1023) / 1024;
    const int NBLK_GEMM = (NN + 127) / 128;

    k_prep<<<512, 128>>>(w1, lin_w, weights);
    k_zero<<<(NN + 255) / 256, 256>>>();
    k_deg<<<(EE + 255) / 256, 256>>>(dst);
    k_scan_block<<<NBLK_SCAN, 1024>>>();
    k_scan_add<<<NBLK_SCAN, 1024>>>();
    k_fill<<<(EE + 255) / 256, 256>>>(src, dst);
    k_pred<<<NBLK_GEMM, 256, PRED_SMEM>>>(x, b1, w2, b2, alpha, emb);
    k_lap1<<<(NN * 32 + 255) / 256, 256>>>();
    k_lap2<<<(NN * 32 + 255) / 256, 256>>>();
    k_final<<<NBLK_GEMM, 256, FIN_SMEM>>>(e, x, x0, lin_b, out);
}

// round 5
// speedup vs baseline: 2.7796x; 1.1693x over previous
#include <cuda_runtime.h>
#include <cuda_fp16.h>
#include <cstdint>

#define NN 100000
#define EE 800000
#define DD 128
#define TH0 0.5f
#define TH1 0.3f
#define TH2 0.2f
#define NEG 0.01f

// smem offsets (bytes)
#define OFFA 0
#define OFFB 32768
#define OFFLP 65536                     // float2[2][128] = 2048
#define OFFPS 67584                     // float[128]
#define PRED_SMEM (OFFPS + 512)
#define FIN_SMEM  65536

// ---------------- device scratch ----------------
__device__ int   g_deg[NN];
__device__ int   g_rowptr[NN + 1];
__device__ int   g_cursor[NN];
__device__ int   g_partials[128];
__device__ float g_dinv[NN];           // deg^-1/2
__device__ float g_rdeg[NN];           // deg^+1/2
__device__ int   g_col[EE];
__device__ __align__(16) __half g_xs0h[NN * DD];       // dinv*xk0 as f16
__device__ __align__(16) __half g_xs1h[NN * DD];       // dinv*xk1 as f16
__device__ __align__(16) __half g_hih[NN * DD];        // hi as f16
__device__ __align__(16) __half g_W1h[128 * 128];      // W1 [n][k] f16
__device__ __align__(16) __half g_Bh[128 * 384];       // combined B [n][kk] f16

// ---------------- helpers ----------------
__device__ __forceinline__ uint32_t smem_u32(const void* p) {
    uint32_t a;
    asm("{ .reg .u64 t; cvta.to.shared.u64 t, %1; cvt.u32.u64 %0, t; }" : "=r"(a) : "l"(p));
    return a;
}
__device__ __forceinline__ void ldsm4(uint32_t* r, uint32_t addr) {
    asm volatile("ldmatrix.sync.aligned.m8n8.x4.shared.b16 {%0,%1,%2,%3}, [%4];"
                 : "=r"(r[0]), "=r"(r[1]), "=r"(r[2]), "=r"(r[3]) : "r"(addr));
}
__device__ __forceinline__ void mma16816(float* c, const uint32_t* a, const uint32_t* b) {
    asm volatile("mma.sync.aligned.m16n8k16.row.col.f32.f16.f16.f32 "
                 "{%0,%1,%2,%3},{%4,%5,%6,%7},{%8,%9},{%0,%1,%2,%3};"
                 : "+f"(c[0]), "+f"(c[1]), "+f"(c[2]), "+f"(c[3])
                 : "r"(a[0]), "r"(a[1]), "r"(a[2]), "r"(a[3]), "r"(b[0]), "r"(b[1]));
}
__device__ __forceinline__ uint4 pack8(float4 a, float4 b) {
    __half2 h0 = __floats2half2_rn(a.x, a.y);
    __half2 h1 = __floats2half2_rn(a.z, a.w);
    __half2 h2 = __floats2half2_rn(b.x, b.y);
    __half2 h3 = __floats2half2_rn(b.z, b.w);
    return make_uint4(*(unsigned*)&h0, *(unsigned*)&h1, *(unsigned*)&h2, *(unsigned*)&h3);
}
__device__ __forceinline__ uint2 pack4(float4 a) {
    __half2 h0 = __floats2half2_rn(a.x, a.y);
    __half2 h1 = __floats2half2_rn(a.z, a.w);
    return make_uint2(*(unsigned*)&h0, *(unsigned*)&h1);
}
__device__ __forceinline__ float4 unpack4(uint2 v) {
    float2 lo = __half22float2(*(__half2*)&v.x);
    float2 hi = __half22float2(*(__half2*)&v.y);
    return make_float4(lo.x, lo.y, hi.x, hi.y);
}
// smem byte address for (row, 16B-chunk) with XOR swizzle, 256B row stride
__device__ __forceinline__ int swz(int row, int chunk) {
    return row * 256 + ((chunk ^ (row & 7)) << 4);
}

// ---------------- prep: f16 operand images + deg zeroing ----------------
__global__ void k_prep(const float* __restrict__ w1,
                       const float* __restrict__ lin_w,
                       const float* __restrict__ weights) {
    int bid = blockIdx.x, t = threadIdx.x;
    if (bid >= 512) {
        int i = (bid - 512) * 128 + t;
        if (i < NN) g_deg[i] = 0;
        return;
    }
    if (bid < 128) {
        g_W1h[bid * 128 + t] = __float2half_rn(w1[bid * 128 + t]);
    } else {
        int kk = bid - 128;            // 0..383
        float v;
        if (kk < 128) {
            v = lin_w[t * 256 + kk];
        } else {
            int r = kk - 128;
            float s = 0.f;
            #pragma unroll 4
            for (int o = 0; o < 128; o++)
                s = fmaf(__ldg(&weights[r * 128 + o]), __ldg(&lin_w[t * 256 + 128 + o]), s);
            v = s;
        }
        g_Bh[t * 384 + kk] = __float2half_rn(v);
    }
}

// ---------------- CSR build ----------------
__global__ void k_deg(const int* __restrict__ dst) {
    int i = blockIdx.x * blockDim.x + threadIdx.x;
    if (i < EE) atomicAdd(&g_deg[dst[i]], 1);
}
__global__ void k_scan_block() {
    __shared__ int s[1024];
    int i = blockIdx.x * 1024 + threadIdx.x;
    int v = (i < NN) ? g_deg[i] : 0;
    s[threadIdx.x] = v;
    __syncthreads();
    for (int off = 1; off < 1024; off <<= 1) {
        int t = (threadIdx.x >= off) ? s[threadIdx.x - off] : 0;
        __syncthreads();
        s[threadIdx.x] += t;
        __syncthreads();
    }
    if (i < NN) g_rowptr[i] = s[threadIdx.x] - v;
    if (threadIdx.x == 1023) g_partials[blockIdx.x] = s[1023];
}
__global__ void k_scan_add() {
    __shared__ int soff;
    if (threadIdx.x == 0) {
        int acc = 0;
        for (int b = 0; b < (int)blockIdx.x; b++) acc += g_partials[b];
        soff = acc;
    }
    __syncthreads();
    int i = blockIdx.x * 1024 + threadIdx.x;
    if (i < NN) {
        int r = g_rowptr[i] + soff;
        g_rowptr[i] = r;
        g_cursor[i] = r;
        int d = g_deg[i];
        float df = (float)(d > 0 ? d : 1);
        g_dinv[i] = rsqrtf(df);
        g_rdeg[i] = sqrtf(df);
        if (i == NN - 1) g_rowptr[NN] = EE;
    }
}
__global__ void k_fill(const int* __restrict__ src, const int* __restrict__ dst) {
    int i = blockIdx.x * blockDim.x + threadIdx.x;
    if (i < EE) {
        int p = atomicAdd(&g_cursor[dst[i]], 1);
        g_col[p] = src[i];
    }
}

// ---------------- predictor: HMMA GEMM + softmax head -> xs0h ----------------
__global__ __launch_bounds__(256)
void k_pred(const float* __restrict__ x, const float* __restrict__ b1,
            const float* __restrict__ w2, const float* __restrict__ b2,
            const float* __restrict__ alpha, const float* __restrict__ emb) {
    extern __shared__ __align__(16) unsigned char sm[];
    uint32_t sbase = smem_u32(sm);
    const int tid = threadIdx.x, lane = tid & 31, wid = tid >> 5;
    const int n0 = blockIdx.x * 128;
    const int rows = min(128, NN - n0);

    for (int i = tid; i < 2048; i += 256) {
        int r = i >> 4, c = i & 15;
        float4 va = make_float4(0.f, 0.f, 0.f, 0.f), vb = va;
        if (r < rows) {
            va = *(const float4*)&x[(n0 + r) * 128 + c * 8];
            vb = *(const float4*)&x[(n0 + r) * 128 + c * 8 + 4];
        }
        *(uint4*)(sm + OFFA + swz(r, c)) = pack8(va, vb);
    }
    for (int i = tid; i < 2048; i += 256) {
        int r = i >> 4, c = i & 15;
        *(uint4*)(sm + OFFB + swz(r, c)) = ((const uint4*)g_W1h)[i];
    }
    __syncthreads();

    const int wm = wid & 3, wn = wid >> 2;
    const int m_base = wm * 32, n_base = wn * 64;
    const int rA0 = m_base + (lane & 15), rA1 = rA0 + 16;
    const int chA = lane >> 4;
    int rB[4];
    #pragma unroll
    for (int np = 0; np < 4; np++)
        rB[np] = n_base + np * 16 + (lane & 7) + ((lane & 16) >> 1);
    const int chB = (lane >> 3) & 1;

    float acc[2][8][4];
    #pragma unroll
    for (int mt = 0; mt < 2; mt++)
        #pragma unroll
        for (int nt = 0; nt < 8; nt++)
            #pragma unroll
            for (int q = 0; q < 4; q++) acc[mt][nt][q] = 0.f;

    #pragma unroll
    for (int ks = 0; ks < 8; ks++) {
        uint32_t af[2][4], bf[4][4];
        ldsm4(af[0], sbase + OFFA + swz(rA0, 2 * ks + chA));
        ldsm4(af[1], sbase + OFFA + swz(rA1, 2 * ks + chA));
        #pragma unroll
        for (int np = 0; np < 4; np++)
            ldsm4(bf[np], sbase + OFFB + swz(rB[np], 2 * ks + chB));
        #pragma unroll
        for (int mt = 0; mt < 2; mt++)
            #pragma unroll
            for (int nt = 0; nt < 8; nt++)
                mma16816(acc[mt][nt], af[mt], &bf[nt >> 1][(nt & 1) * 2]);
    }
    __syncthreads();

    float lp0[2][2] = {{0.f, 0.f}, {0.f, 0.f}};
    float lp1[2][2] = {{0.f, 0.f}, {0.f, 0.f}};
    #pragma unroll
    for (int nt = 0; nt < 8; nt++) {
        int col = n_base + nt * 8 + 2 * (lane & 3);
        float b1a = __ldg(&b1[col]), b1b = __ldg(&b1[col + 1]);
        float wa0 = __ldg(&w2[col]), wb0 = __ldg(&w2[col + 1]);
        float wa1 = __ldg(&w2[128 + col]), wb1 = __ldg(&w2[128 + col + 1]);
        #pragma unroll
        for (int mt = 0; mt < 2; mt++)
            #pragma unroll
            for (int rh = 0; rh < 2; rh++) {
                float h0 = fmaxf(acc[mt][nt][2 * rh] + b1a, 0.f);
                float h1 = fmaxf(acc[mt][nt][2 * rh + 1] + b1b, 0.f);
                lp0[mt][rh] += h0 * wa0 + h1 * wb0;
                lp1[mt][rh] += h0 * wa1 + h1 * wb1;
            }
    }
    float2* Lp = (float2*)(sm + OFFLP);
    #pragma unroll
    for (int mt = 0; mt < 2; mt++)
        #pragma unroll
        for (int rh = 0; rh < 2; rh++) {
            float a0 = lp0[mt][rh], a1 = lp1[mt][rh];
            a0 += __shfl_xor_sync(0xFFFFFFFF, a0, 1);
            a0 += __shfl_xor_sync(0xFFFFFFFF, a0, 2);
            a1 += __shfl_xor_sync(0xFFFFFFFF, a1, 1);
            a1 += __shfl_xor_sync(0xFFFFFFFF, a1, 2);
            if ((lane & 3) == 0) {
                int row = m_base + mt * 16 + (lane >> 2) + rh * 8;
                Lp[wn * 128 + row] = make_float2(a0, a1);
            }
        }
    __syncthreads();

    float* Ps = (float*)(sm + OFFPS);
    if (tid < 128) {
        float2 u = Lp[tid], v = Lp[128 + tid];
        float l0 = u.x + v.x + __ldg(&b2[0]);
        float l1 = u.y + v.y + __ldg(&b2[1]);
        Ps[tid] = 1.f / (1.f + expf(l0 - l1));
    }
    __syncthreads();

    const float al = __ldg(&alpha[0]);
    for (int idx = tid; idx < 128 * 32; idx += 256) {
        int m = idx >> 5, cq = (idx & 31) * 4;
        if (m < rows) {
            float p = Ps[m];
            float dv = __ldg(&g_dinv[n0 + m]);
            float4 xv = *(const float4*)&x[(n0 + m) * 128 + cq];
            float4 e0 = *(const float4*)&emb[cq];
            float4 e1 = *(const float4*)&emb[128 + cq];
            float4 s;
            s.x = (xv.x + al * ((1.f - p) * e0.x + p * e1.x)) * dv;
            s.y = (xv.y + al * ((1.f - p) * e0.y + p * e1.y)) * dv;
            s.z = (xv.z + al * ((1.f - p) * e0.z + p * e1.z)) * dv;
            s.w = (xv.w + al * ((1.f - p) * e0.w + p * e1.w)) * dv;
            ((uint2*)g_xs0h)[(n0 + m) * 32 + (idx & 31)] = pack4(s);
        }
    }
}

// ---------------- Laplacian passes (all-f16 scaled state) ----------------
// xs1 = xs0 - acc * dinv^2
__global__ __launch_bounds__(256)
void k_lap1() {
    int gw = (blockIdx.x * blockDim.x + threadIdx.x) >> 5;
    if (gw >= NN) return;
    int lane = threadIdx.x & 31;
    const uint2* xs = (const uint2*)g_xs0h;
    int beg = g_rowptr[gw], end = g_rowptr[gw + 1];
    float4 acc = make_float4(0.f, 0.f, 0.f, 0.f);
    #pragma unroll 4
    for (int ei = beg; ei < end; ei++) {
        int u = __ldg(&g_col[ei]);
        float4 v = unpack4(__ldg(&xs[u * 32 + lane]));
        acc.x += v.x; acc.y += v.y; acc.z += v.z; acc.w += v.w;
    }
    float dv = g_dinv[gw];
    float d2 = dv * dv;
    float4 xv = unpack4(xs[gw * 32 + lane]);
    float4 r;
    r.x = xv.x - acc.x * d2; r.y = xv.y - acc.y * d2;
    r.z = xv.z - acc.z * d2; r.w = xv.w - acc.w * d2;
    ((uint2*)g_xs1h)[gw * 32 + lane] = pack4(r);
}
// hi = rdeg*(TH0*xs0 + (TH1+TH2)*xs1) - TH2*acc*dinv
__global__ __launch_bounds__(256)
void k_lap2() {
    int gw = (blockIdx.x * blockDim.x + threadIdx.x) >> 5;
    if (gw >= NN) return;
    int lane = threadIdx.x & 31;
    const uint2* xs = (const uint2*)g_xs1h;
    int beg = g_rowptr[gw], end = g_rowptr[gw + 1];
    float4 acc = make_float4(0.f, 0.f, 0.f, 0.f);
    #pragma unroll 4
    for (int ei = beg; ei < end; ei++) {
        int u = __ldg(&g_col[ei]);
        float4 v = unpack4(__ldg(&xs[u * 32 + lane]));
        acc.x += v.x; acc.y += v.y; acc.z += v.z; acc.w += v.w;
    }
    float dv = g_dinv[gw];
    float rd = g_rdeg[gw];
    float4 v0 = unpack4(((const uint2*)g_xs0h)[gw * 32 + lane]);
    float4 v1 = unpack4(xs[gw * 32 + lane]);
    const float c1 = TH1 + TH2;
    float4 r;
    r.x = rd * (TH0 * v0.x + c1 * v1.x) - TH2 * (acc.x * dv);
    r.y = rd * (TH0 * v0.y + c1 * v1.y) - TH2 * (acc.y * dv);
    r.z = rd * (TH0 * v0.z + c1 * v1.z) - TH2 * (acc.z * dv);
    r.w = rd * (TH0 * v0.w + c1 * v1.w) - TH2 * (acc.w * dv);
    ((uint2*)g_hih)[gw * 32 + lane] = pack4(r);
}

// ---------------- final: HMMA GEMM (K=384, 3 segs) + leaky + x0 ----------------
__global__ __launch_bounds__(256)
void k_final(const float* __restrict__ e, const float* __restrict__ x,
             const float* __restrict__ x0, const float* __restrict__ linb,
             float* __restrict__ out) {
    extern __shared__ __align__(16) unsigned char sm[];
    uint32_t sbase = smem_u32(sm);
    const int tid = threadIdx.x, lane = tid & 31, wid = tid >> 5;
    const int n0 = blockIdx.x * 128;
    const int rows = min(128, NN - n0);

    const int wm = wid & 3, wn = wid >> 2;
    const int m_base = wm * 32, n_base = wn * 64;
    const int rA0 = m_base + (lane & 15), rA1 = rA0 + 16;
    const int chA = lane >> 4;
    int rB[4];
    #pragma unroll
    for (int np = 0; np < 4; np++)
        rB[np] = n_base + np * 16 + (lane & 7) + ((lane & 16) >> 1);
    const int chB = (lane >> 3) & 1;

    float acc[2][8][4];
    #pragma unroll
    for (int mt = 0; mt < 2; mt++)
        #pragma unroll
        for (int nt = 0; nt < 8; nt++)
            #pragma unroll
            for (int q = 0; q < 4; q++) acc[mt][nt][q] = 0.f;

    for (int s = 0; s < 3; s++) {
        if (s == 1) {
            for (int i = tid; i < 2048; i += 256) {
                int r = i >> 4, c = i & 15;
                uint4 v = make_uint4(0u, 0u, 0u, 0u);
                if (r < rows) v = ((const uint4*)g_hih)[(n0 + r) * 16 + c];
                *(uint4*)(sm + OFFA + swz(r, c)) = v;
            }
        } else {
            const float* srcm = (s == 0) ? e : x;
            for (int i = tid; i < 2048; i += 256) {
                int r = i >> 4, c = i & 15;
                float4 va = make_float4(0.f, 0.f, 0.f, 0.f), vb = va;
                if (r < rows) {
                    va = *(const float4*)&srcm[(n0 + r) * 128 + c * 8];
                    vb = *(const float4*)&srcm[(n0 + r) * 128 + c * 8 + 4];
                }
                *(uint4*)(sm + OFFA + swz(r, c)) = pack8(va, vb);
            }
        }
        for (int i = tid; i < 2048; i += 256) {
            int r = i >> 4, c = i & 15;
            *(uint4*)(sm + OFFB + swz(r, c)) = ((const uint4*)g_Bh)[r * 48 + s * 16 + c];
        }
        __syncthreads();

        #pragma unroll
        for (int ks = 0; ks < 8; ks++) {
            uint32_t af[2][4], bf[4][4];
            ldsm4(af[0], sbase + OFFA + swz(rA0, 2 * ks + chA));
            ldsm4(af[1], sbase + OFFA + swz(rA1, 2 * ks + chA));
            #pragma unroll
            for (int np = 0; np < 4; np++)
                ldsm4(bf[np], sbase + OFFB + swz(rB[np], 2 * ks + chB));
            #pragma unroll
            for (int mt = 0; mt < 2; mt++)
                #pragma unroll
                for (int nt = 0; nt < 8; nt++)
                    mma16816(acc[mt][nt], af[mt], &bf[nt >> 1][(nt & 1) * 2]);
        }
        __syncthreads();
    }

    #pragma unroll
    for (int mt = 0; mt < 2; mt++)
        #pragma unroll
        for (int rh = 0; rh < 2; rh++) {
            int row = m_base + mt * 16 + (lane >> 2) + rh * 8;
            if (row < rows) {
                int m = n0 + row;
                #pragma unroll
                for (int nt = 0; nt < 8; nt++) {
                    int col = n_base + nt * 8 + 2 * (lane & 3);
                    float v0 = acc[mt][nt][2 * rh]     + __ldg(&linb[col]);
                    float v1 = acc[mt][nt][2 * rh + 1] + __ldg(&linb[col + 1]);
                    v0 = v0 > 0.f ? v0 : NEG * v0;
                    v1 = v1 > 0.f ? v1 : NEG * v1;
                    float2 xb = *(const float2*)&x0[m * 128 + col];
                    *(float2*)&out[m * 128 + col] = make_float2(v0 + xb.x, v1 + xb.y);
                }
            }
        }
}

// ---------------- launcher ----------------
extern "C" void kernel_launch(void* const* d_in, const int* in_sizes, int n_in,
                              void* d_out, int out_size) {
    const int*   src     = (const int*)  d_in[0];
    const int*   dst     = (const int*)  d_in[1];
    const float* x0      = (const float*)d_in[2];
    const float* x       = (const float*)d_in[3];
    const float* e       = (const float*)d_in[4];
    const float* alpha   = (const float*)d_in[7];
    const float* emb     = (const float*)d_in[8];
    const float* w1      = (const float*)d_in[9];
    const float* b1      = (const float*)d_in[10];
    const float* w2      = (const float*)d_in[11];
    const float* b2      = (const float*)d_in[12];
    const float* weights = (const float*)d_in[13];
    const float* lin_w   = (const float*)d_in[14];
    const float* lin_b   = (const float*)d_in[15];
    float* out = (float*)d_out;

    cudaFuncSetAttribute(k_pred,  cudaFuncAttributeMaxDynamicSharedMemorySize, PRED_SMEM);
    cudaFuncSetAttribute(k_final, cudaFuncAttributeMaxDynamicSharedMemorySize, FIN_SMEM);

    const int NBLK_SCAN = (NN + 1023) / 1024;
    const int NBLK_GEMM = (NN + 127) / 128;
    const int NBLK_ZERO = (NN + 127) / 128;

    k_prep<<<512 + NBLK_ZERO, 128>>>(w1, lin_w, weights);
    k_deg<<<(EE + 255) / 256, 256>>>(dst);
    k_scan_block<<<NBLK_SCAN, 1024>>>();
    k_scan_add<<<NBLK_SCAN, 1024>>>();
    k_fill<<<(EE + 255) / 256, 256>>>(src, dst);
    k_pred<<<NBLK_GEMM, 256, PRED_SMEM>>>(x, b1, w2, b2, alpha, emb);
    k_lap1<<<(NN * 32 + 255) / 256, 256>>>();
    k_lap2<<<(NN * 32 + 255) / 256, 256>>>();
    k_final<<<NBLK_GEMM, 256, FIN_SMEM>>>(e, x, x0, lin_b, out);
}

// round 7
// speedup vs baseline: 2.8219x; 1.0152x over previous
#include <cuda_runtime.h>
#include <cuda_fp16.h>
#include <cstdint>

#define NN 100000
#define EE 800000
#define DD 128
#define TH0 0.5f
#define TH1 0.3f
#define TH2 0.2f
#define NEG 0.01f

// smem offsets (bytes)
#define OFFA 0
#define OFFB 32768
#define OFFLP 65536                     // float2[2][128] = 2048
#define OFFPS 67584                     // float[128]
#define PRED_SMEM (OFFPS + 512)
#define FIN_SMEM  65536

// ---------------- device scratch ----------------
__device__ int   g_deg[NN];
__device__ int   g_rowptr[NN + 1];
__device__ int   g_cursor[NN];
__device__ int   g_partials[128];
__device__ float g_dinv[NN];           // deg^-1/2
__device__ float g_rdeg[NN];           // deg^+1/2
__device__ int   g_col[EE];
__device__ __align__(16) __half g_xs0h[NN * DD];       // dinv*xk0 as f16
__device__ __align__(16) __half g_xs1h[NN * DD];       // dinv*xk1 as f16
__device__ __align__(16) __half g_hih[NN * DD];        // hi as f16
__device__ __align__(16) __half g_W1h[128 * 128];      // W1 [n][k] f16
__device__ __align__(16) __half g_Bh[128 * 384];       // combined B [n][kk] f16

// ---------------- helpers ----------------
__device__ __forceinline__ uint32_t smem_u32(const void* p) {
    uint32_t a;
    asm("{ .reg .u64 t; cvta.to.shared.u64 t, %1; cvt.u32.u64 %0, t; }" : "=r"(a) : "l"(p));
    return a;
}
__device__ __forceinline__ void ldsm4(uint32_t* r, uint32_t addr) {
    asm volatile("ldmatrix.sync.aligned.m8n8.x4.shared.b16 {%0,%1,%2,%3}, [%4];"
                 : "=r"(r[0]), "=r"(r[1]), "=r"(r[2]), "=r"(r[3]) : "r"(addr));
}
__device__ __forceinline__ void mma16816(float* c, const uint32_t* a, const uint32_t* b) {
    asm volatile("mma.sync.aligned.m16n8k16.row.col.f32.f16.f16.f32 "
                 "{%0,%1,%2,%3},{%4,%5,%6,%7},{%8,%9},{%0,%1,%2,%3};"
                 : "+f"(c[0]), "+f"(c[1]), "+f"(c[2]), "+f"(c[3])
                 : "r"(a[0]), "r"(a[1]), "r"(a[2]), "r"(a[3]), "r"(b[0]), "r"(b[1]));
}
__device__ __forceinline__ uint4 pack8(float4 a, float4 b) {
    __half2 h0 = __floats2half2_rn(a.x, a.y);
    __half2 h1 = __floats2half2_rn(a.z, a.w);
    __half2 h2 = __floats2half2_rn(b.x, b.y);
    __half2 h3 = __floats2half2_rn(b.z, b.w);
    return make_uint4(*(unsigned*)&h0, *(unsigned*)&h1, *(unsigned*)&h2, *(unsigned*)&h3);
}
__device__ __forceinline__ uint2 pack4(float4 a) {
    __half2 h0 = __floats2half2_rn(a.x, a.y);
    __half2 h1 = __floats2half2_rn(a.z, a.w);
    return make_uint2(*(unsigned*)&h0, *(unsigned*)&h1);
}
__device__ __forceinline__ float4 unpack4(uint2 v) {
    float2 lo = __half22float2(*(__half2*)&v.x);
    float2 hi = __half22float2(*(__half2*)&v.y);
    return make_float4(lo.x, lo.y, hi.x, hi.y);
}
// smem byte address for (row, 16B-chunk) with XOR swizzle, 256B row stride
__device__ __forceinline__ int swz(int row, int chunk) {
    return row * 256 + ((chunk ^ (row & 7)) << 4);
}

// ---------------- prep: f16 operand images ----------------
__global__ void k_prep(const float* __restrict__ w1,
                       const float* __restrict__ lin_w,
                       const float* __restrict__ weights) {
    int bid = blockIdx.x, t = threadIdx.x;
    if (bid < 128) {
        g_W1h[bid * 128 + t] = __float2half_rn(w1[bid * 128 + t]);
    } else {
        int kk = bid - 128;            // 0..383
        float v;
        if (kk < 128) {
            v = lin_w[t * 256 + kk];
        } else {
            int r = kk - 128;
            float s = 0.f;
            #pragma unroll 4
            for (int o = 0; o < 128; o++)
                s = fmaf(__ldg(&weights[r * 128 + o]), __ldg(&lin_w[t * 256 + 128 + o]), s);
            v = s;
        }
        g_Bh[t * 384 + kk] = __float2half_rn(v);
    }
}

// ---------------- CSR build ----------------
__global__ void k_zero() {
    int i = blockIdx.x * blockDim.x + threadIdx.x;
    if (i < NN) g_deg[i] = 0;
}
__global__ void k_deg(const int* __restrict__ dst) {
    int i = blockIdx.x * blockDim.x + threadIdx.x;
    if (i < EE) atomicAdd(&g_deg[dst[i]], 1);
}
__global__ void k_dinv() {
    int i = blockIdx.x * blockDim.x + threadIdx.x;
    if (i < NN) {
        int d = g_deg[i];
        float df = (float)(d > 0 ? d : 1);
        g_dinv[i] = rsqrtf(df);
        g_rdeg[i] = sqrtf(df);
    }
}
__global__ void k_scan_block() {
    __shared__ int s[1024];
    int i = blockIdx.x * 1024 + threadIdx.x;
    int v = (i < NN) ? g_deg[i] : 0;
    s[threadIdx.x] = v;
    __syncthreads();
    for (int off = 1; off < 1024; off <<= 1) {
        int t = (threadIdx.x >= off) ? s[threadIdx.x - off] : 0;
        __syncthreads();
        s[threadIdx.x] += t;
        __syncthreads();
    }
    if (i < NN) g_rowptr[i] = s[threadIdx.x] - v;
    if (threadIdx.x == 1023) g_partials[blockIdx.x] = s[1023];
}
__global__ void k_scan_add() {
    __shared__ int s[128];
    int bid = blockIdx.x;
    if (threadIdx.x < 128)
        s[threadIdx.x] = (threadIdx.x < bid) ? g_partials[threadIdx.x] : 0;
    __syncthreads();
    #pragma unroll
    for (int off = 64; off > 0; off >>= 1) {
        if (threadIdx.x < off) s[threadIdx.x] += s[threadIdx.x + off];
        __syncthreads();
    }
    int soff = s[0];
    int i = bid * 1024 + threadIdx.x;
    if (i < NN) {
        int r = g_rowptr[i] + soff;
        g_rowptr[i] = r;
        g_cursor[i] = r;
        if (i == NN - 1) g_rowptr[NN] = EE;
    }
}
__global__ void k_fill(const int* __restrict__ src, const int* __restrict__ dst) {
    int i = blockIdx.x * blockDim.x + threadIdx.x;
    if (i < EE) {
        int p = atomicAdd(&g_cursor[dst[i]], 1);
        g_col[p] = src[i];
    }
}

// ---------------- predictor: HMMA GEMM + softmax head -> xs0h ----------------
__global__ __launch_bounds__(256)
void k_pred(const float* __restrict__ x, const float* __restrict__ b1,
            const float* __restrict__ w2, const float* __restrict__ b2,
            const float* __restrict__ alpha, const float* __restrict__ emb) {
    extern __shared__ __align__(16) unsigned char sm[];
    uint32_t sbase = smem_u32(sm);
    const int tid = threadIdx.x, lane = tid & 31, wid = tid >> 5;
    const int n0 = blockIdx.x * 128;
    const int rows = min(128, NN - n0);

    for (int i = tid; i < 2048; i += 256) {
        int r = i >> 4, c = i & 15;
        float4 va = make_float4(0.f, 0.f, 0.f, 0.f), vb = va;
        if (r < rows) {
            va = *(const float4*)&x[(n0 + r) * 128 + c * 8];
            vb = *(const float4*)&x[(n0 + r) * 128 + c * 8 + 4];
        }
        *(uint4*)(sm + OFFA + swz(r, c)) = pack8(va, vb);
    }
    for (int i = tid; i < 2048; i += 256) {
        int r = i >> 4, c = i & 15;
        *(uint4*)(sm + OFFB + swz(r, c)) = ((const uint4*)g_W1h)[i];
    }
    __syncthreads();

    const int wm = wid & 3, wn = wid >> 2;
    const int m_base = wm * 32, n_base = wn * 64;
    const int rA0 = m_base + (lane & 15), rA1 = rA0 + 16;
    const int chA = lane >> 4;
    int rB[4];
    #pragma unroll
    for (int np = 0; np < 4; np++)
        rB[np] = n_base + np * 16 + (lane & 7) + ((lane & 16) >> 1);
    const int chB = (lane >> 3) & 1;

    float acc[2][8][4];
    #pragma unroll
    for (int mt = 0; mt < 2; mt++)
        #pragma unroll
        for (int nt = 0; nt < 8; nt++)
            #pragma unroll
            for (int q = 0; q < 4; q++) acc[mt][nt][q] = 0.f;

    #pragma unroll
    for (int ks = 0; ks < 8; ks++) {
        uint32_t af[2][4], bf[4][4];
        ldsm4(af[0], sbase + OFFA + swz(rA0, 2 * ks + chA));
        ldsm4(af[1], sbase + OFFA + swz(rA1, 2 * ks + chA));
        #pragma unroll
        for (int np = 0; np < 4; np++)
            ldsm4(bf[np], sbase + OFFB + swz(rB[np], 2 * ks + chB));
        #pragma unroll
        for (int mt = 0; mt < 2; mt++)
            #pragma unroll
            for (int nt = 0; nt < 8; nt++)
                mma16816(acc[mt][nt], af[mt], &bf[nt >> 1][(nt & 1) * 2]);
    }
    __syncthreads();

    float lp0[2][2] = {{0.f, 0.f}, {0.f, 0.f}};
    float lp1[2][2] = {{0.f, 0.f}, {0.f, 0.f}};
    #pragma unroll
    for (int nt = 0; nt < 8; nt++) {
        int col = n_base + nt * 8 + 2 * (lane & 3);
        float b1a = __ldg(&b1[col]), b1b = __ldg(&b1[col + 1]);
        float wa0 = __ldg(&w2[col]), wb0 = __ldg(&w2[col + 1]);
        float wa1 = __ldg(&w2[128 + col]), wb1 = __ldg(&w2[128 + col + 1]);
        #pragma unroll
        for (int mt = 0; mt < 2; mt++)
            #pragma unroll
            for (int rh = 0; rh < 2; rh++) {
                float h0 = fmaxf(acc[mt][nt][2 * rh] + b1a, 0.f);
                float h1 = fmaxf(acc[mt][nt][2 * rh + 1] + b1b, 0.f);
                lp0[mt][rh] += h0 * wa0 + h1 * wb0;
                lp1[mt][rh] += h0 * wa1 + h1 * wb1;
            }
    }
    float2* Lp = (float2*)(sm + OFFLP);
    #pragma unroll
    for (int mt = 0; mt < 2; mt++)
        #pragma unroll
        for (int rh = 0; rh < 2; rh++) {
            float a0 = lp0[mt][rh], a1 = lp1[mt][rh];
            a0 += __shfl_xor_sync(0xFFFFFFFF, a0, 1);
            a0 += __shfl_xor_sync(0xFFFFFFFF, a0, 2);
            a1 += __shfl_xor_sync(0xFFFFFFFF, a1, 1);
            a1 += __shfl_xor_sync(0xFFFFFFFF, a1, 2);
            if ((lane & 3) == 0) {
                int row = m_base + mt * 16 + (lane >> 2) + rh * 8;
                Lp[wn * 128 + row] = make_float2(a0, a1);
            }
        }
    __syncthreads();

    float* Ps = (float*)(sm + OFFPS);
    if (tid < 128) {
        float2 u = Lp[tid], v = Lp[128 + tid];
        float l0 = u.x + v.x + __ldg(&b2[0]);
        float l1 = u.y + v.y + __ldg(&b2[1]);
        Ps[tid] = 1.f / (1.f + expf(l0 - l1));
    }
    __syncthreads();

    // epilogue: xs0 = (x + alpha*node)*dinv, reading x back from f16 smem tile
    const float al = __ldg(&alpha[0]);
    for (int idx = tid; idx < 128 * 16; idx += 256) {
        int m = idx >> 4, c = idx & 15;
        if (m < rows) {
            float p = Ps[m];
            float dv = __ldg(&g_dinv[n0 + m]);
            uint4 xv4 = *(uint4*)(sm + OFFA + swz(m, c));
            __half2* hp = (__half2*)&xv4;
            uint4 ov;
            unsigned* op = (unsigned*)&ov;
            #pragma unroll
            for (int j = 0; j < 4; j++) {
                float2 f = __half22float2(hp[j]);
                int cc = c * 8 + j * 2;
                float n0v = (1.f - p) * __ldg(&emb[cc])     + p * __ldg(&emb[128 + cc]);
                float n1v = (1.f - p) * __ldg(&emb[cc + 1]) + p * __ldg(&emb[128 + cc + 1]);
                __half2 h = __floats2half2_rn((f.x + al * n0v) * dv, (f.y + al * n1v) * dv);
                op[j] = *(unsigned*)&h;
            }
            ((uint4*)g_xs0h)[(n0 + m) * 16 + c] = ov;
        }
    }
}

// ---------------- Laplacian passes (all-f16 scaled state) ----------------
__global__ __launch_bounds__(256)
void k_lap1() {
    int gw = (blockIdx.x * blockDim.x + threadIdx.x) >> 5;
    if (gw >= NN) return;
    int lane = threadIdx.x & 31;
    const uint2* xs = (const uint2*)g_xs0h;
    int beg = g_rowptr[gw], end = g_rowptr[gw + 1];
    float4 acc = make_float4(0.f, 0.f, 0.f, 0.f);
    #pragma unroll 4
    for (int ei = beg; ei < end; ei++) {
        int u = __ldg(&g_col[ei]);
        float4 v = unpack4(__ldg(&xs[u * 32 + lane]));
        acc.x += v.x; acc.y += v.y; acc.z += v.z; acc.w += v.w;
    }
    float dv = g_dinv[gw];
    float d2 = dv * dv;
    float4 xv = unpack4(xs[gw * 32 + lane]);
    float4 r;
    r.x = xv.x - acc.x * d2; r.y = xv.y - acc.y * d2;
    r.z = xv.z - acc.z * d2; r.w = xv.w - acc.w * d2;
    ((uint2*)g_xs1h)[gw * 32 + lane] = pack4(r);
}
__global__ __launch_bounds__(256)
void k_lap2() {
    int gw = (blockIdx.x * blockDim.x + threadIdx.x) >> 5;
    if (gw >= NN) return;
    int lane = threadIdx.x & 31;
    const uint2* xs = (const uint2*)g_xs1h;
    int beg = g_rowptr[gw], end = g_rowptr[gw + 1];
    float4 acc = make_float4(0.f, 0.f, 0.f, 0.f);
    #pragma unroll 4
    for (int ei = beg; ei < end; ei++) {
        int u = __ldg(&g_col[ei]);
        float4 v = unpack4(__ldg(&xs[u * 32 + lane]));
        acc.x += v.x; acc.y += v.y; acc.z += v.z; acc.w += v.w;
    }
    float dv = g_dinv[gw];
    float rd = g_rdeg[gw];
    float4 v0 = unpack4(((const uint2*)g_xs0h)[gw * 32 + lane]);
    float4 v1 = unpack4(xs[gw * 32 + lane]);
    const float c1 = TH1 + TH2;
    float4 r;
    r.x = rd * (TH0 * v0.x + c1 * v1.x) - TH2 * (acc.x * dv);
    r.y = rd * (TH0 * v0.y + c1 * v1.y) - TH2 * (acc.y * dv);
    r.z = rd * (TH0 * v0.z + c1 * v1.z) - TH2 * (acc.z * dv);
    r.w = rd * (TH0 * v0.w + c1 * v1.w) - TH2 * (acc.w * dv);
    ((uint2*)g_hih)[gw * 32 + lane] = pack4(r);
}

// ---------------- final: HMMA GEMM (K=384, 3 segs) + leaky + x0 ----------------
__global__ __launch_bounds__(256)
void k_final(const float* __restrict__ e, const float* __restrict__ x,
             const float* __restrict__ x0, const float* __restrict__ linb,
             float* __restrict__ out) {
    extern __shared__ __align__(16) unsigned char sm[];
    uint32_t sbase = smem_u32(sm);
    const int tid = threadIdx.x, lane = tid & 31, wid = tid >> 5;
    const int n0 = blockIdx.x * 128;
    const int rows = min(128, NN - n0);

    const int wm = wid & 3, wn = wid >> 2;
    const int m_base = wm * 32, n_base = wn * 64;
    const int rA0 = m_base + (lane & 15), rA1 = rA0 + 16;
    const int chA = lane >> 4;
    int rB[4];
    #pragma unroll
    for (int np = 0; np < 4; np++)
        rB[np] = n_base + np * 16 + (lane & 7) + ((lane & 16) >> 1);
    const int chB = (lane >> 3) & 1;

    float acc[2][8][4];
    #pragma unroll
    for (int mt = 0; mt < 2; mt++)
        #pragma unroll
        for (int nt = 0; nt < 8; nt++)
            #pragma unroll
            for (int q = 0; q < 4; q++) acc[mt][nt][q] = 0.f;

    for (int s = 0; s < 3; s++) {
        if (s == 1) {
            for (int i = tid; i < 2048; i += 256) {
                int r = i >> 4, c = i & 15;
                uint4 v = make_uint4(0u, 0u, 0u, 0u);
                if (r < rows) v = ((const uint4*)g_hih)[(n0 + r) * 16 + c];
                *(uint4*)(sm + OFFA + swz(r, c)) = v;
            }
        } else {
            const float* srcm = (s == 0) ? e : x;
            for (int i = tid; i < 2048; i += 256) {
                int r = i >> 4, c = i & 15;
                float4 va = make_float4(0.f, 0.f, 0.f, 0.f), vb = va;
                if (r < rows) {
                    va = *(const float4*)&srcm[(n0 + r) * 128 + c * 8];
                    vb = *(const float4*)&srcm[(n0 + r) * 128 + c * 8 + 4];
                }
                *(uint4*)(sm + OFFA + swz(r, c)) = pack8(va, vb);
            }
        }
        for (int i = tid; i < 2048; i += 256) {
            int r = i >> 4, c = i & 15;
            *(uint4*)(sm + OFFB + swz(r, c)) = ((const uint4*)g_Bh)[r * 48 + s * 16 + c];
        }
        __syncthreads();

        #pragma unroll
        for (int ks = 0; ks < 8; ks++) {
            uint32_t af[2][4], bf[4][4];
            ldsm4(af[0], sbase + OFFA + swz(rA0, 2 * ks + chA));
            ldsm4(af[1], sbase + OFFA + swz(rA1, 2 * ks + chA));
            #pragma unroll
            for (int np = 0; np < 4; np++)
                ldsm4(bf[np], sbase + OFFB + swz(rB[np], 2 * ks + chB));
            #pragma unroll
            for (int mt = 0; mt < 2; mt++)
                #pragma unroll
                for (int nt = 0; nt < 8; nt++)
                    mma16816(acc[mt][nt], af[mt], &bf[nt >> 1][(nt & 1) * 2]);
        }
        __syncthreads();
    }

    #pragma unroll
    for (int mt = 0; mt < 2; mt++)
        #pragma unroll
        for (int rh = 0; rh < 2; rh++) {
            int row = m_base + mt * 16 + (lane >> 2) + rh * 8;
            if (row < rows) {
                int m = n0 + row;
                #pragma unroll
                for (int nt = 0; nt < 8; nt++) {
                    int col = n_base + nt * 8 + 2 * (lane & 3);
                    float v0 = acc[mt][nt][2 * rh]     + __ldg(&linb[col]);
                    float v1 = acc[mt][nt][2 * rh + 1] + __ldg(&linb[col + 1]);
                    v0 = v0 > 0.f ? v0 : NEG * v0;
                    v1 = v1 > 0.f ? v1 : NEG * v1;
                    float2 xb = *(const float2*)&x0[m * 128 + col];
                    *(float2*)&out[m * 128 + col] = make_float2(v0 + xb.x, v1 + xb.y);
                }
            }
        }
}

// ---------------- launcher (stream-fork overlap) ----------------
extern "C" void kernel_launch(void* const* d_in, const int* in_sizes, int n_in,
                              void* d_out, int out_size) {
    const int*   src     = (const int*)  d_in[0];
    const int*   dst     = (const int*)  d_in[1];
    const float* x0      = (const float*)d_in[2];
    const float* x       = (const float*)d_in[3];
    const float* e       = (const float*)d_in[4];
    const float* alpha   = (const float*)d_in[7];
    const float* emb     = (const float*)d_in[8];
    const float* w1      = (const float*)d_in[9];
    const float* b1      = (const float*)d_in[10];
    const float* w2      = (const float*)d_in[11];
    const float* b2      = (const float*)d_in[12];
    const float* weights = (const float*)d_in[13];
    const float* lin_w   = (const float*)d_in[14];
    const float* lin_b   = (const float*)d_in[15];
    float* out = (float*)d_out;

    static cudaStream_t sB = nullptr;
    static cudaEvent_t ev0 = nullptr, evD = nullptr, evP = nullptr;
    if (!sB) {
        cudaStreamCreateWithFlags(&sB, cudaStreamNonBlocking);
        cudaEventCreateWithFlags(&ev0, cudaEventDisableTiming);
        cudaEventCreateWithFlags(&evD, cudaEventDisableTiming);
        cudaEventCreateWithFlags(&evP, cudaEventDisableTiming);
    }

    cudaFuncSetAttribute(k_pred,  cudaFuncAttributeMaxDynamicSharedMemorySize, PRED_SMEM);
    cudaFuncSetAttribute(k_final, cudaFuncAttributeMaxDynamicSharedMemorySize, FIN_SMEM);

    const int NBLK_SCAN = (NN + 1023) / 1024;
    const int NBLK_GEMM = (NN + 127) / 128;

    // fork side stream
    cudaEventRecord(ev0, 0);
    cudaStreamWaitEvent(sB, ev0, 0);

    // side stream: weight images
    k_prep<<<512, 128, 0, sB>>>(w1, lin_w, weights);

    // main stream: degree + dinv (k_pred's only CSR dependency)
    k_zero<<<(NN + 255) / 256, 256>>>();
    k_deg<<<(EE + 255) / 256, 256>>>(dst);
    k_dinv<<<(NN + 255) / 256, 256>>>();
    cudaEventRecord(evD, 0);

    // side stream: predictor GEMM (needs dinv + W1h)
    cudaStreamWaitEvent(sB, evD, 0);
    k_pred<<<NBLK_GEMM, 256, PRED_SMEM, sB>>>(x, b1, w2, b2, alpha, emb);
    cudaEventRecord(evP, sB);

    // main stream: finish CSR concurrently with k_pred
    k_scan_block<<<NBLK_SCAN, 1024>>>();
    k_scan_add<<<NBLK_SCAN, 1024>>>();
    k_fill<<<(EE + 255) / 256, 256>>>(src, dst);

    // join, then Laplacians + final GEMM
    cudaStreamWaitEvent(0, evP, 0);
    k_lap1<<<(NN * 32 + 255) / 256, 256>>>();
    k_lap2<<<(NN * 32 + 255) / 256, 256>>>();
    k_final<<<NBLK_GEMM, 256, FIN_SMEM>>>(e, x, x0, lin_b, out);
}